// round 11
// baseline (speedup 1.0000x reference)
#include <cuda_runtime.h>
#include <cuda_fp16.h>
#include <math.h>
#include <stdint.h>

// ---------------------------------------------------------------------------
// Shape (fixed): B=512, T=128, E=512, FF=2048
// ---------------------------------------------------------------------------
#define B_   512
#define T_   128
#define E_   512
#define FF_  2048
#define ROWS (B_ * T_)          // 65536

// ---------------------------------------------------------------------------
// Scratch (device globals). Pure fp16 activations and weights.
// ---------------------------------------------------------------------------
__device__ __half g_h_hi [ROWS * E_];
__device__ __half g_h2_hi[ROWS * E_];
__device__ __half g_m1_hi[ROWS * FF_];
__device__ float  g_q [ROWS * E_], g_k[ROWS * E_], g_v[ROWS * E_];
__device__ float  g_att[B_ * T_ * T_];
__device__ __half g_wqt[E_ * E_];
__device__ __half g_wkt[E_ * E_];
__device__ __half g_wvt[E_ * E_];
__device__ __half g_w1t[FF_ * E_];
__device__ __half g_w2t[E_ * FF_];

// ---------------------------------------------------------------------------
// Baseline-PTX helpers
// ---------------------------------------------------------------------------
__device__ __forceinline__ uint32_t smem_u32(const void* p) {
    uint32_t a;
    asm("{ .reg .u64 t; cvta.to.shared.u64 t, %1; cvt.u32.u64 %0, t; }"
        : "=r"(a) : "l"(p));
    return a;
}
__device__ __forceinline__ void cp_async16(uint32_t dst, const void* src) {
    asm volatile("cp.async.cg.shared.global [%0], [%1], 16;" :: "r"(dst), "l"(src));
}
__device__ __forceinline__ void cp_commit() {
    asm volatile("cp.async.commit_group;" ::: "memory");
}
__device__ __forceinline__ void cp_wait0() {
    asm volatile("cp.async.wait_group 0;" ::: "memory");
}
__device__ __forceinline__ void cp_wait1() {
    asm volatile("cp.async.wait_group 1;" ::: "memory");
}

#define LDSM_X4(r, addr) \
    asm volatile("ldmatrix.sync.aligned.m8n8.x4.shared.b16 {%0,%1,%2,%3}, [%4];" \
        : "=r"((r)[0]), "=r"((r)[1]), "=r"((r)[2]), "=r"((r)[3]) : "r"(addr))

__device__ __forceinline__ void mma16816(float* c, const uint32_t* a,
                                         uint32_t b0, uint32_t b1) {
    asm volatile(
        "mma.sync.aligned.m16n8k16.row.col.f32.f16.f16.f32 "
        "{%0,%1,%2,%3}, {%4,%5,%6,%7}, {%8,%9}, {%0,%1,%2,%3};"
        : "+f"(c[0]), "+f"(c[1]), "+f"(c[2]), "+f"(c[3])
        : "r"(a[0]), "r"(a[1]), "r"(a[2]), "r"(a[3]), "r"(b0), "r"(b1));
}

__device__ __forceinline__ float gelu_exact(float x) {
    return 0.5f * x * (1.0f + erff(x * 0.7071067811865476f));
}

// ---------------------------------------------------------------------------
// HMMA GEMM, 128 threads (4 warps, 2x2), warp tile 64x64, occupancy 2.
// BM=128, BN=128, BK=32, pure fp16, 2-stage cp.async.
// Stage segs (halves): A @0 | B @5120 ; stage = 10240 halves (20KB)
// ---------------------------------------------------------------------------
#define GBM 128
#define GBN 128
#define GSTRIDE 40
#define SEG_HALVES 5120                       // 128*40
#define STAGE_HALVES 10240                    // 2*5120
static constexpr int GEMM_SMEM_BYTES = 2 * STAGE_HALVES * 2;  // 40960

template<int ACT, int OUTM>
__global__ __launch_bounds__(128, 2)
void gemm_mma_kernel(const __half* __restrict__ A,
                     const __half* __restrict__ B,
                     const float* __restrict__ bias, const float* __restrict__ res,
                     float* __restrict__ Cf, __half* __restrict__ Chi,
                     int Ntot, int K)
{
    extern __shared__ __half sm[];
    const int tid = threadIdx.x, wid = tid >> 5, lane = tid & 31;
    const int m0 = blockIdx.y * GBM;
    const int n0 = blockIdx.x * GBN;
    const uint32_t smb = smem_u32(sm);

    const __half* ptrA = A + (size_t)m0 * K;
    const __half* ptrB = B + (size_t)n0 * K;

    auto load_stage = [&](int st, int k0) {
        const uint32_t base = smb + (uint32_t)st * (STAGE_HALVES * 2);
        #pragma unroll
        for (int it = 0; it < 8; ++it) {
            const int i = tid + it * 128;            // 0..1023
            const int seg = i >> 9;                  // 0 A, 1 B
            const int j = i & 511;
            const int row = j >> 2, col = (j & 3) * 8;
            const __half* src = (seg == 0 ? ptrA : ptrB) + (size_t)row * K + k0 + col;
            const uint32_t dst = base + (uint32_t)((seg * SEG_HALVES + row * GSTRIDE + col) * 2);
            cp_async16(dst, src);
        }
    };

    float acc[4][8][4];
    #pragma unroll
    for (int mt = 0; mt < 4; ++mt)
        #pragma unroll
        for (int nt = 0; nt < 8; ++nt)
            #pragma unroll
            for (int e = 0; e < 4; ++e) acc[mt][nt][e] = 0.0f;

    const int wm = (wid >> 1) * 64;       // 2 m-groups of 64
    const int wn = (wid & 1) * 64;        // 2 n-groups of 64
    const int NC = K >> 5;

    load_stage(0, 0);
    cp_commit();

    for (int c = 0; c < NC; ++c) {
        if (c + 1 < NC) {
            load_stage((c + 1) & 1, (c + 1) * 32);
            cp_commit();
            cp_wait1();
        } else {
            cp_wait0();
        }
        __syncthreads();

        const uint32_t sb = smb + (uint32_t)(c & 1) * (STAGE_HALVES * 2);
        #pragma unroll
        for (int kk = 0; kk < 32; kk += 16) {
            uint32_t bh[8][2];
            #pragma unroll
            for (int ng = 0; ng < 4; ++ng) {
                const uint32_t addr = sb +
                    (uint32_t)((SEG_HALVES + (wn + ng * 16 + (lane & 15)) * GSTRIDE
                                + kk + ((lane >> 4) << 3)) << 1);
                uint32_t r[4];
                LDSM_X4(r, addr);
                bh[2 * ng][0] = r[0]; bh[2 * ng][1] = r[2];
                bh[2 * ng + 1][0] = r[1]; bh[2 * ng + 1][1] = r[3];
            }
            uint32_t ah[4][4];
            #pragma unroll
            for (int mt = 0; mt < 4; ++mt) {
                const uint32_t addr = sb +
                    (uint32_t)(((wm + mt * 16 + (lane & 15)) * GSTRIDE
                                + kk + ((lane >> 4) << 3)) << 1);
                LDSM_X4(ah[mt], addr);
            }
            #pragma unroll
            for (int mt = 0; mt < 4; ++mt)
                #pragma unroll
                for (int nt = 0; nt < 8; ++nt)
                    mma16816(acc[mt][nt], ah[mt], bh[nt][0], bh[nt][1]);
        }
        __syncthreads();
    }

    // epilogue
    #pragma unroll
    for (int mt = 0; mt < 4; ++mt) {
        const int r0 = m0 + wm + mt * 16 + (lane >> 2);
        const int r1 = r0 + 8;
        #pragma unroll
        for (int nt = 0; nt < 8; ++nt) {
            const int col = n0 + wn + nt * 8 + (lane & 3) * 2;
            const float bia0 = __ldg(&bias[col]);
            const float bia1 = __ldg(&bias[col + 1]);
            float v00 = acc[mt][nt][0] + bia0;
            float v01 = acc[mt][nt][1] + bia1;
            float v10 = acc[mt][nt][2] + bia0;
            float v11 = acc[mt][nt][3] + bia1;
            if (ACT == 1) {
                v00 = gelu_exact(v00); v01 = gelu_exact(v01);
                v10 = gelu_exact(v10); v11 = gelu_exact(v11);
            }
            if (OUTM == 0) {
                if (res) {
                    const float2 q0 = *(const float2*)(res + (size_t)r0 * Ntot + col);
                    const float2 q1 = *(const float2*)(res + (size_t)r1 * Ntot + col);
                    v00 += q0.x; v01 += q0.y; v10 += q1.x; v11 += q1.y;
                }
                *(float2*)(Cf + (size_t)r0 * Ntot + col) = make_float2(v00, v01);
                *(float2*)(Cf + (size_t)r1 * Ntot + col) = make_float2(v10, v11);
            } else {
                *(__half2*)(Chi + (size_t)r0 * Ntot + col) =
                    __halves2half2(__float2half_rn(v00), __float2half_rn(v01));
                *(__half2*)(Chi + (size_t)r1 * Ntot + col) =
                    __halves2half2(__float2half_rn(v10), __float2half_rn(v11));
            }
        }
    }
}

// ---------------------------------------------------------------------------
// QK^T + scale + causal mask + softmax fused (R6-validated). One block/batch.
// ---------------------------------------------------------------------------
__global__ __launch_bounds__(256, 2)
void qk_softmax_kernel(const float* __restrict__ Q, const float* __restrict__ Km,
                       float* __restrict__ P)
{
    const int b = blockIdx.x;
    const float* Ab = Q  + (size_t)b * T_ * E_;
    const float* Bb = Km + (size_t)b * T_ * E_;

    __shared__ float As[16][128];
    __shared__ float Bs[16][128];
    __shared__ float red [128][17];
    __shared__ float red2[128][17];
    const int tid = threadIdx.x;
    const int tx = tid & 15, ty = tid >> 4;

    float acc[8][8];
    #pragma unroll
    for (int i = 0; i < 8; i++)
        #pragma unroll
        for (int j = 0; j < 8; j++) acc[i][j] = 0.0f;

    for (int k0 = 0; k0 < E_; k0 += 16) {
        #pragma unroll
        for (int l = 0; l < 2; l++) {
            const int vidx = tid + l * 256;
            const int ar = vidx >> 2, ac = (vidx & 3) * 4;
            const float4 ta = *(const float4*)&Ab[(size_t)ar * E_ + k0 + ac];
            As[ac + 0][ar] = ta.x; As[ac + 1][ar] = ta.y;
            As[ac + 2][ar] = ta.z; As[ac + 3][ar] = ta.w;
            const float4 tb = *(const float4*)&Bb[(size_t)ar * E_ + k0 + ac];
            Bs[ac + 0][ar] = tb.x; Bs[ac + 1][ar] = tb.y;
            Bs[ac + 2][ar] = tb.z; Bs[ac + 3][ar] = tb.w;
        }
        __syncthreads();
        #pragma unroll
        for (int kk = 0; kk < 16; kk++) {
            float a[8], bb[8];
            *(float4*)&a[0]  = *(const float4*)&As[kk][ty * 4];
            *(float4*)&a[4]  = *(const float4*)&As[kk][64 + ty * 4];
            *(float4*)&bb[0] = *(const float4*)&Bs[kk][tx * 4];
            *(float4*)&bb[4] = *(const float4*)&Bs[kk][64 + tx * 4];
            #pragma unroll
            for (int i = 0; i < 8; i++)
                #pragma unroll
                for (int j = 0; j < 8; j++)
                    acc[i][j] += a[i] * bb[j];
        }
        __syncthreads();
    }

    #pragma unroll
    for (int i = 0; i < 8; i++) {
        const int r = (i < 4) ? (ty * 4 + i) : (64 + ty * 4 + i - 4);
        float m = -INFINITY;
        #pragma unroll
        for (int j = 0; j < 8; j++) {
            const int c = (j < 4) ? (tx * 4 + j) : (64 + tx * 4 + j - 4);
            float v = acc[i][j] * 0.125f;
            if (c > r) v = -INFINITY;
            acc[i][j] = v;
            m = fmaxf(m, v);
        }
        red[r][tx] = m;
    }
    __syncthreads();
    if (tid < 128) {
        float m = red[tid][0];
        #pragma unroll
        for (int t = 1; t < 16; t++) m = fmaxf(m, red[tid][t]);
        red[tid][16] = m;
    }
    __syncthreads();
    #pragma unroll
    for (int i = 0; i < 8; i++) {
        const int r = (i < 4) ? (ty * 4 + i) : (64 + ty * 4 + i - 4);
        const float m = red[r][16];
        float s = 0.0f;
        #pragma unroll
        for (int j = 0; j < 8; j++) {
            const float p = expf(acc[i][j] - m);
            acc[i][j] = p;
            s += p;
        }
        red2[r][tx] = s;
    }
    __syncthreads();
    if (tid < 128) {
        float s = red2[tid][0];
        #pragma unroll
        for (int t = 1; t < 16; t++) s += red2[tid][t];
        red2[tid][16] = 1.0f / s;
    }
    __syncthreads();

    float* Pb = P + (size_t)b * T_ * T_;
    #pragma unroll
    for (int i = 0; i < 8; i++) {
        const int r = (i < 4) ? (ty * 4 + i) : (64 + ty * 4 + i - 4);
        const float inv = red2[r][16];
        #pragma unroll
        for (int jh = 0; jh < 2; jh++) {
            const int c0 = jh * 64 + tx * 4;
            *(float4*)&Pb[(size_t)r * T_ + c0] =
                make_float4(acc[i][jh * 4 + 0] * inv, acc[i][jh * 4 + 1] * inv,
                            acc[i][jh * 4 + 2] * inv, acc[i][jh * 4 + 3] * inv);
        }
    }
}

// ---------------------------------------------------------------------------
// O = X + P @ V (batched). grid=(4, 512). (R1-validated)
// ---------------------------------------------------------------------------
__global__ __launch_bounds__(256, 2)
void pv_kernel(const float* __restrict__ P, const float* __restrict__ V,
               const float* __restrict__ X, float* __restrict__ O)
{
    const int b  = blockIdx.y;
    const int n0 = blockIdx.x * 128;
    const float* Ab = P + (size_t)b * T_ * T_;
    const float* Bb = V + (size_t)b * T_ * E_;

    __shared__ float As[16][128];
    __shared__ float Bs[16][128];
    const int tid = threadIdx.x;
    const int tx = tid & 15, ty = tid >> 4;

    float acc[8][8];
    #pragma unroll
    for (int i = 0; i < 8; i++)
        #pragma unroll
        for (int j = 0; j < 8; j++) acc[i][j] = 0.0f;

    for (int k0 = 0; k0 < T_; k0 += 16) {
        #pragma unroll
        for (int l = 0; l < 2; l++) {
            const int vidx = tid + l * 256;
            const int ar = vidx >> 2, ac = (vidx & 3) * 4;
            const float4 ta = *(const float4*)&Ab[(size_t)ar * T_ + k0 + ac];
            As[ac + 0][ar] = ta.x; As[ac + 1][ar] = ta.y;
            As[ac + 2][ar] = ta.z; As[ac + 3][ar] = ta.w;
            const int br = vidx >> 5, bc = (vidx & 31) * 4;
            *(float4*)&Bs[br][bc] = *(const float4*)&Bb[(size_t)(k0 + br) * E_ + n0 + bc];
        }
        __syncthreads();
        #pragma unroll
        for (int kk = 0; kk < 16; kk++) {
            float a[8], bb[8];
            *(float4*)&a[0]  = *(const float4*)&As[kk][ty * 4];
            *(float4*)&a[4]  = *(const float4*)&As[kk][64 + ty * 4];
            *(float4*)&bb[0] = *(const float4*)&Bs[kk][tx * 4];
            *(float4*)&bb[4] = *(const float4*)&Bs[kk][64 + tx * 4];
            #pragma unroll
            for (int i = 0; i < 8; i++)
                #pragma unroll
                for (int j = 0; j < 8; j++)
                    acc[i][j] += a[i] * bb[j];
        }
        __syncthreads();
    }

    #pragma unroll
    for (int i = 0; i < 8; i++) {
        const int t = (i < 4) ? (ty * 4 + i) : (64 + ty * 4 + i - 4);
        const size_t rowbase = ((size_t)b * T_ + t) * E_;
        #pragma unroll
        for (int jh = 0; jh < 2; jh++) {
            const int c0 = n0 + jh * 64 + tx * 4;
            const float4 xr = *(const float4*)&X[rowbase + c0];
            float4 o;
            o.x = xr.x + acc[i][jh * 4 + 0];
            o.y = xr.y + acc[i][jh * 4 + 1];
            o.z = xr.z + acc[i][jh * 4 + 2];
            o.w = xr.w + acc[i][jh * 4 + 3];
            *(float4*)&O[rowbase + c0] = o;
        }
    }
}

// ---------------------------------------------------------------------------
// LayerNorm -> fp16 output
// ---------------------------------------------------------------------------
__global__ void ln_f16_kernel(const float* __restrict__ X,
                              const float* __restrict__ g,
                              const float* __restrict__ b,
                              __half* __restrict__ Ohi)
{
    const int row = blockIdx.x;
    const int tid = threadIdx.x;
    const int lane = tid & 31, wid = tid >> 5;

    const float4 v = ((const float4*)(X + (size_t)row * E_))[tid];
    float s  = v.x + v.y + v.z + v.w;
    float sq = v.x * v.x + v.y * v.y + v.z * v.z + v.w * v.w;

    #pragma unroll
    for (int off = 16; off > 0; off >>= 1) {
        s  += __shfl_xor_sync(0xffffffffu, s,  off);
        sq += __shfl_xor_sync(0xffffffffu, sq, off);
    }
    __shared__ float ss[4], ssq[4];
    if (lane == 0) { ss[wid] = s; ssq[wid] = sq; }
    __syncthreads();
    s  = ss[0]  + ss[1]  + ss[2]  + ss[3];
    sq = ssq[0] + ssq[1] + ssq[2] + ssq[3];

    const float mean = s * (1.0f / E_);
    const float var  = sq * (1.0f / E_) - mean * mean;
    const float inv  = rsqrtf(var + 1e-5f);

    const float4 gg = ((const float4*)g)[tid];
    const float4 bb = ((const float4*)b)[tid];
    const float o0 = (v.x - mean) * inv * gg.x + bb.x;
    const float o1 = (v.y - mean) * inv * gg.y + bb.y;
    const float o2 = (v.z - mean) * inv * gg.z + bb.z;
    const float o3 = (v.w - mean) * inv * gg.w + bb.w;

    __half2* ph = (__half2*)(Ohi + (size_t)row * E_);
    ph[tid * 2 + 0] = __halves2half2(__float2half_rn(o0), __float2half_rn(o1));
    ph[tid * 2 + 1] = __halves2half2(__float2half_rn(o2), __float2half_rn(o3));
}

// ---------------------------------------------------------------------------
// Merged transpose (fp32 -> fp16) for all 5 weights in ONE launch.
// ---------------------------------------------------------------------------
__global__ void transpose_all(
    const float* __restrict__ wq, const float* __restrict__ wk,
    const float* __restrict__ wv, const float* __restrict__ w1,
    const float* __restrict__ w2,
    __half* __restrict__ qt, __half* __restrict__ kt,
    __half* __restrict__ vt, __half* __restrict__ o1t,
    __half* __restrict__ o2t)
{
    __shared__ float tile[32][33];
    const int bid = blockIdx.x;
    const float* W; __half* Th;
    int Kdim, Ndim, t;
    if (bid < 768) {
        t = bid & 255; Kdim = E_; Ndim = E_;
        if (bid < 256)      { W = wq; Th = qt; }
        else if (bid < 512) { W = wk; Th = kt; }
        else                { W = wv; Th = vt; }
    } else if (bid < 1792) {
        t = bid - 768; Kdim = E_; Ndim = FF_;
        W = w1; Th = o1t;
    } else {
        t = bid - 1792; Kdim = FF_; Ndim = E_;
        W = w2; Th = o2t;
    }
    const int nblocks = Ndim / 32;
    const int n0 = (t % nblocks) * 32, k0 = (t / nblocks) * 32;
    const int tx = threadIdx.x, ty = threadIdx.y;   // (32, 8)
    #pragma unroll
    for (int i = 0; i < 4; ++i)
        tile[ty + i * 8][tx] = W[(size_t)(k0 + ty + i * 8) * Ndim + n0 + tx];
    __syncthreads();
    #pragma unroll
    for (int i = 0; i < 4; ++i) {
        const float v = tile[tx][ty + i * 8];
        const size_t o = (size_t)(n0 + ty + i * 8) * Kdim + k0 + tx;
        Th[o] = __float2half_rn(v);
    }
}

// ---------------------------------------------------------------------------
// Launch
// ---------------------------------------------------------------------------
extern "C" void kernel_launch(void* const* d_in, const int* in_sizes, int n_in,
                              void* d_out, int out_size)
{
    const float* x   = (const float*)d_in[0];
    const float* wq  = (const float*)d_in[1];
    const float* bq  = (const float*)d_in[2];
    const float* wk  = (const float*)d_in[3];
    const float* bk  = (const float*)d_in[4];
    const float* wv  = (const float*)d_in[5];
    const float* bv  = (const float*)d_in[6];
    const float* g1  = (const float*)d_in[7];
    const float* b1  = (const float*)d_in[8];
    const float* g2  = (const float*)d_in[9];
    const float* b2  = (const float*)d_in[10];
    const float* w1  = (const float*)d_in[11];
    const float* bm1 = (const float*)d_in[12];
    const float* w2  = (const float*)d_in[13];
    const float* bm2 = (const float*)d_in[14];
    float* out = (float*)d_out;

    __half *h_hi, *h2_hi, *m1_hi;
    __half *wqt, *wkt, *wvt, *w1t, *w2t;
    float *q, *k, *v, *att;
    cudaGetSymbolAddress((void**)&h_hi,  g_h_hi);
    cudaGetSymbolAddress((void**)&h2_hi, g_h2_hi);
    cudaGetSymbolAddress((void**)&m1_hi, g_m1_hi);
    cudaGetSymbolAddress((void**)&wqt, g_wqt);
    cudaGetSymbolAddress((void**)&wkt, g_wkt);
    cudaGetSymbolAddress((void**)&wvt, g_wvt);
    cudaGetSymbolAddress((void**)&w1t, g_w1t);
    cudaGetSymbolAddress((void**)&w2t, g_w2t);
    cudaGetSymbolAddress((void**)&q, g_q); cudaGetSymbolAddress((void**)&k, g_k);
    cudaGetSymbolAddress((void**)&v, g_v); cudaGetSymbolAddress((void**)&att, g_att);

    cudaFuncSetAttribute(gemm_mma_kernel<0, 0>, cudaFuncAttributeMaxDynamicSharedMemorySize, GEMM_SMEM_BYTES);
    cudaFuncSetAttribute(gemm_mma_kernel<1, 1>, cudaFuncAttributeMaxDynamicSharedMemorySize, GEMM_SMEM_BYTES);

    transpose_all<<<2816, dim3(32, 8)>>>(wq, wk, wv, w1, w2, wqt, wkt, wvt, w1t, w2t);

    ln_f16_kernel<<<ROWS, 128>>>(x, g1, b1, h_hi);

    const dim3 gQKV(E_ / GBN, ROWS / GBM);     // (4, 512)
    gemm_mma_kernel<0, 0><<<gQKV, 128, GEMM_SMEM_BYTES>>>(h_hi, wqt, bq, nullptr, q, nullptr, E_, E_);
    gemm_mma_kernel<0, 0><<<gQKV, 128, GEMM_SMEM_BYTES>>>(h_hi, wkt, bk, nullptr, k, nullptr, E_, E_);
    gemm_mma_kernel<0, 0><<<gQKV, 128, GEMM_SMEM_BYTES>>>(h_hi, wvt, bv, nullptr, v, nullptr, E_, E_);

    qk_softmax_kernel<<<B_, 256>>>(q, k, att);
    pv_kernel<<<dim3(E_ / 128, B_), 256>>>(att, v, x, out);

    ln_f16_kernel<<<ROWS, 128>>>(out, g2, b2, h2_hi);

    gemm_mma_kernel<1, 1><<<dim3(FF_ / GBN, ROWS / GBM), 128, GEMM_SMEM_BYTES>>>(
        h2_hi, w1t, bm1, nullptr, nullptr, m1_hi, FF_, E_);

    gemm_mma_kernel<0, 0><<<dim3(E_ / GBN, ROWS / GBM), 128, GEMM_SMEM_BYTES>>>(
        m1_hi, w2t, bm2, out, out, nullptr, E_, FF_);
}

// round 12
// speedup vs baseline: 1.0957x; 1.0957x over previous
#include <cuda_runtime.h>
#include <cuda_fp16.h>
#include <math.h>
#include <stdint.h>

// ---------------------------------------------------------------------------
// Shape (fixed): B=512, T=128, E=512, FF=2048
// ---------------------------------------------------------------------------
#define B_   512
#define T_   128
#define E_   512
#define FF_  2048
#define ROWS (B_ * T_)          // 65536

// ---------------------------------------------------------------------------
// Scratch (device globals). Pure fp16 activations and weights.
// ---------------------------------------------------------------------------
__device__ __half g_h_hi [ROWS * E_];
__device__ __half g_h2_hi[ROWS * E_];
__device__ __half g_m1_hi[ROWS * FF_];
__device__ float  g_q [ROWS * E_], g_k[ROWS * E_], g_v[ROWS * E_];
__device__ float  g_att[B_ * T_ * T_];
__device__ __half g_wqt[E_ * E_];
__device__ __half g_wkt[E_ * E_];
__device__ __half g_wvt[E_ * E_];
__device__ __half g_w1t[FF_ * E_];
__device__ __half g_w2t[E_ * FF_];

// ---------------------------------------------------------------------------
// Baseline-PTX helpers
// ---------------------------------------------------------------------------
__device__ __forceinline__ uint32_t smem_u32(const void* p) {
    uint32_t a;
    asm("{ .reg .u64 t; cvta.to.shared.u64 t, %1; cvt.u32.u64 %0, t; }"
        : "=r"(a) : "l"(p));
    return a;
}
__device__ __forceinline__ void cp_async16(uint32_t dst, const void* src) {
    asm volatile("cp.async.cg.shared.global [%0], [%1], 16;" :: "r"(dst), "l"(src));
}
__device__ __forceinline__ void cp_commit() {
    asm volatile("cp.async.commit_group;" ::: "memory");
}
__device__ __forceinline__ void cp_wait0() {
    asm volatile("cp.async.wait_group 0;" ::: "memory");
}
__device__ __forceinline__ void cp_wait1() {
    asm volatile("cp.async.wait_group 1;" ::: "memory");
}

#define LDSM_X4(r, addr) \
    asm volatile("ldmatrix.sync.aligned.m8n8.x4.shared.b16 {%0,%1,%2,%3}, [%4];" \
        : "=r"((r)[0]), "=r"((r)[1]), "=r"((r)[2]), "=r"((r)[3]) : "r"(addr))

__device__ __forceinline__ void mma16816(float* c, const uint32_t* a,
                                         uint32_t b0, uint32_t b1) {
    asm volatile(
        "mma.sync.aligned.m16n8k16.row.col.f32.f16.f16.f32 "
        "{%0,%1,%2,%3}, {%4,%5,%6,%7}, {%8,%9}, {%0,%1,%2,%3};"
        : "+f"(c[0]), "+f"(c[1]), "+f"(c[2]), "+f"(c[3])
        : "r"(a[0]), "r"(a[1]), "r"(a[2]), "r"(a[3]), "r"(b0), "r"(b1));
}

__device__ __forceinline__ float gelu_exact(float x) {
    return 0.5f * x * (1.0f + erff(x * 0.7071067811865476f));
}

// ---------------------------------------------------------------------------
// HMMA GEMM, 256 threads (8 warps 4x2), warp tile 32x64, occupancy 2.
// BM=128, BN=128, BK=64 (amortize barriers), pure fp16, 2-stage cp.async.
// Stage segs (halves): A @0 | B @9216 ; stage = 18432 halves (36KB)
// ---------------------------------------------------------------------------
#define GBM 128
#define GBN 128
#define GSTRIDE 72
#define SEG_HALVES 9216                       // 128*72
#define STAGE_HALVES 18432                    // 2*9216
static constexpr int GEMM_SMEM_BYTES = 2 * STAGE_HALVES * 2;  // 73728

template<int ACT, int OUTM>
__global__ __launch_bounds__(256, 2)
void gemm_mma_kernel(const __half* __restrict__ A,
                     const __half* __restrict__ B,
                     const float* __restrict__ bias, const float* __restrict__ res,
                     float* __restrict__ Cf, __half* __restrict__ Chi,
                     int Ntot, int K)
{
    extern __shared__ __half sm[];
    const int tid = threadIdx.x, wid = tid >> 5, lane = tid & 31;
    const int m0 = blockIdx.y * GBM;
    const int n0 = blockIdx.x * GBN;
    const uint32_t smb = smem_u32(sm);

    const __half* ptrA = A + (size_t)m0 * K;
    const __half* ptrB = B + (size_t)n0 * K;

    // stage = 128 rows x 64 halves (8 chunks of 16B) for A and B
    auto load_stage = [&](int st, int k0) {
        const uint32_t base = smb + (uint32_t)st * (STAGE_HALVES * 2);
        #pragma unroll
        for (int it = 0; it < 8; ++it) {
            const int i = tid + it * 256;            // 0..2047
            const int seg = i >> 10;                 // 0 A, 1 B
            const int j = i & 1023;
            const int row = j >> 3, ch = j & 7;
            const __half* src = (seg == 0 ? ptrA : ptrB) + (size_t)row * K + k0 + ch * 8;
            const uint32_t dst = base + (uint32_t)((seg * SEG_HALVES + row * GSTRIDE + ch * 8) * 2);
            cp_async16(dst, src);
        }
    };

    float acc[2][8][4];
    #pragma unroll
    for (int mt = 0; mt < 2; ++mt)
        #pragma unroll
        for (int nt = 0; nt < 8; ++nt)
            #pragma unroll
            for (int e = 0; e < 4; ++e) acc[mt][nt][e] = 0.0f;

    const int wm = (wid >> 1) * 32;       // 4 m-groups of 32
    const int wn = (wid & 1) * 64;        // 2 n-groups of 64
    const int NC = K >> 6;                // 64-wide chunks

    load_stage(0, 0);
    cp_commit();

    for (int c = 0; c < NC; ++c) {
        if (c + 1 < NC) {
            load_stage((c + 1) & 1, (c + 1) * 64);
            cp_commit();
            cp_wait1();
        } else {
            cp_wait0();
        }
        __syncthreads();

        const uint32_t sb = smb + (uint32_t)(c & 1) * (STAGE_HALVES * 2);
        #pragma unroll
        for (int kk = 0; kk < 64; kk += 16) {
            uint32_t bh[8][2];
            #pragma unroll
            for (int ng = 0; ng < 4; ++ng) {
                const uint32_t addr = sb +
                    (uint32_t)((SEG_HALVES + (wn + ng * 16 + (lane & 15)) * GSTRIDE
                                + kk + ((lane >> 4) << 3)) << 1);
                uint32_t r[4];
                LDSM_X4(r, addr);
                bh[2 * ng][0] = r[0]; bh[2 * ng][1] = r[2];
                bh[2 * ng + 1][0] = r[1]; bh[2 * ng + 1][1] = r[3];
            }
            uint32_t ah[2][4];
            #pragma unroll
            for (int mt = 0; mt < 2; ++mt) {
                const uint32_t addr = sb +
                    (uint32_t)(((wm + mt * 16 + (lane & 15)) * GSTRIDE
                                + kk + ((lane >> 4) << 3)) << 1);
                LDSM_X4(ah[mt], addr);
            }
            #pragma unroll
            for (int mt = 0; mt < 2; ++mt)
                #pragma unroll
                for (int nt = 0; nt < 8; ++nt)
                    mma16816(acc[mt][nt], ah[mt], bh[nt][0], bh[nt][1]);
        }
        __syncthreads();
    }

    // epilogue
    #pragma unroll
    for (int mt = 0; mt < 2; ++mt) {
        const int r0 = m0 + wm + mt * 16 + (lane >> 2);
        const int r1 = r0 + 8;
        #pragma unroll
        for (int nt = 0; nt < 8; ++nt) {
            const int col = n0 + wn + nt * 8 + (lane & 3) * 2;
            const float bia0 = __ldg(&bias[col]);
            const float bia1 = __ldg(&bias[col + 1]);
            float v00 = acc[mt][nt][0] + bia0;
            float v01 = acc[mt][nt][1] + bia1;
            float v10 = acc[mt][nt][2] + bia0;
            float v11 = acc[mt][nt][3] + bia1;
            if (ACT == 1) {
                v00 = gelu_exact(v00); v01 = gelu_exact(v01);
                v10 = gelu_exact(v10); v11 = gelu_exact(v11);
            }
            if (OUTM == 0) {
                if (res) {
                    const float2 q0 = *(const float2*)(res + (size_t)r0 * Ntot + col);
                    const float2 q1 = *(const float2*)(res + (size_t)r1 * Ntot + col);
                    v00 += q0.x; v01 += q0.y; v10 += q1.x; v11 += q1.y;
                }
                *(float2*)(Cf + (size_t)r0 * Ntot + col) = make_float2(v00, v01);
                *(float2*)(Cf + (size_t)r1 * Ntot + col) = make_float2(v10, v11);
            } else {
                *(__half2*)(Chi + (size_t)r0 * Ntot + col) =
                    __halves2half2(__float2half_rn(v00), __float2half_rn(v01));
                *(__half2*)(Chi + (size_t)r1 * Ntot + col) =
                    __halves2half2(__float2half_rn(v10), __float2half_rn(v11));
            }
        }
    }
}

// ---------------------------------------------------------------------------
// QK^T + scale + causal mask + softmax fused (R6-validated). One block/batch.
// ---------------------------------------------------------------------------
__global__ __launch_bounds__(256, 2)
void qk_softmax_kernel(const float* __restrict__ Q, const float* __restrict__ Km,
                       float* __restrict__ P)
{
    const int b = blockIdx.x;
    const float* Ab = Q  + (size_t)b * T_ * E_;
    const float* Bb = Km + (size_t)b * T_ * E_;

    __shared__ float As[16][128];
    __shared__ float Bs[16][128];
    __shared__ float red [128][17];
    __shared__ float red2[128][17];
    const int tid = threadIdx.x;
    const int tx = tid & 15, ty = tid >> 4;

    float acc[8][8];
    #pragma unroll
    for (int i = 0; i < 8; i++)
        #pragma unroll
        for (int j = 0; j < 8; j++) acc[i][j] = 0.0f;

    for (int k0 = 0; k0 < E_; k0 += 16) {
        #pragma unroll
        for (int l = 0; l < 2; l++) {
            const int vidx = tid + l * 256;
            const int ar = vidx >> 2, ac = (vidx & 3) * 4;
            const float4 ta = *(const float4*)&Ab[(size_t)ar * E_ + k0 + ac];
            As[ac + 0][ar] = ta.x; As[ac + 1][ar] = ta.y;
            As[ac + 2][ar] = ta.z; As[ac + 3][ar] = ta.w;
            const float4 tb = *(const float4*)&Bb[(size_t)ar * E_ + k0 + ac];
            Bs[ac + 0][ar] = tb.x; Bs[ac + 1][ar] = tb.y;
            Bs[ac + 2][ar] = tb.z; Bs[ac + 3][ar] = tb.w;
        }
        __syncthreads();
        #pragma unroll
        for (int kk = 0; kk < 16; kk++) {
            float a[8], bb[8];
            *(float4*)&a[0]  = *(const float4*)&As[kk][ty * 4];
            *(float4*)&a[4]  = *(const float4*)&As[kk][64 + ty * 4];
            *(float4*)&bb[0] = *(const float4*)&Bs[kk][tx * 4];
            *(float4*)&bb[4] = *(const float4*)&Bs[kk][64 + tx * 4];
            #pragma unroll
            for (int i = 0; i < 8; i++)
                #pragma unroll
                for (int j = 0; j < 8; j++)
                    acc[i][j] += a[i] * bb[j];
        }
        __syncthreads();
    }

    #pragma unroll
    for (int i = 0; i < 8; i++) {
        const int r = (i < 4) ? (ty * 4 + i) : (64 + ty * 4 + i - 4);
        float m = -INFINITY;
        #pragma unroll
        for (int j = 0; j < 8; j++) {
            const int c = (j < 4) ? (tx * 4 + j) : (64 + tx * 4 + j - 4);
            float v = acc[i][j] * 0.125f;
            if (c > r) v = -INFINITY;
            acc[i][j] = v;
            m = fmaxf(m, v);
        }
        red[r][tx] = m;
    }
    __syncthreads();
    if (tid < 128) {
        float m = red[tid][0];
        #pragma unroll
        for (int t = 1; t < 16; t++) m = fmaxf(m, red[tid][t]);
        red[tid][16] = m;
    }
    __syncthreads();
    #pragma unroll
    for (int i = 0; i < 8; i++) {
        const int r = (i < 4) ? (ty * 4 + i) : (64 + ty * 4 + i - 4);
        const float m = red[r][16];
        float s = 0.0f;
        #pragma unroll
        for (int j = 0; j < 8; j++) {
            const float p = expf(acc[i][j] - m);
            acc[i][j] = p;
            s += p;
        }
        red2[r][tx] = s;
    }
    __syncthreads();
    if (tid < 128) {
        float s = red2[tid][0];
        #pragma unroll
        for (int t = 1; t < 16; t++) s += red2[tid][t];
        red2[tid][16] = 1.0f / s;
    }
    __syncthreads();

    float* Pb = P + (size_t)b * T_ * T_;
    #pragma unroll
    for (int i = 0; i < 8; i++) {
        const int r = (i < 4) ? (ty * 4 + i) : (64 + ty * 4 + i - 4);
        const float inv = red2[r][16];
        #pragma unroll
        for (int jh = 0; jh < 2; jh++) {
            const int c0 = jh * 64 + tx * 4;
            *(float4*)&Pb[(size_t)r * T_ + c0] =
                make_float4(acc[i][jh * 4 + 0] * inv, acc[i][jh * 4 + 1] * inv,
                            acc[i][jh * 4 + 2] * inv, acc[i][jh * 4 + 3] * inv);
        }
    }
}

// ---------------------------------------------------------------------------
// O = X + P @ V (batched). grid=(4, 512). (R1-validated)
// ---------------------------------------------------------------------------
__global__ __launch_bounds__(256, 2)
void pv_kernel(const float* __restrict__ P, const float* __restrict__ V,
               const float* __restrict__ X, float* __restrict__ O)
{
    const int b  = blockIdx.y;
    const int n0 = blockIdx.x * 128;
    const float* Ab = P + (size_t)b * T_ * T_;
    const float* Bb = V + (size_t)b * T_ * E_;

    __shared__ float As[16][128];
    __shared__ float Bs[16][128];
    const int tid = threadIdx.x;
    const int tx = tid & 15, ty = tid >> 4;

    float acc[8][8];
    #pragma unroll
    for (int i = 0; i < 8; i++)
        #pragma unroll
        for (int j = 0; j < 8; j++) acc[i][j] = 0.0f;

    for (int k0 = 0; k0 < T_; k0 += 16) {
        #pragma unroll
        for (int l = 0; l < 2; l++) {
            const int vidx = tid + l * 256;
            const int ar = vidx >> 2, ac = (vidx & 3) * 4;
            const float4 ta = *(const float4*)&Ab[(size_t)ar * T_ + k0 + ac];
            As[ac + 0][ar] = ta.x; As[ac + 1][ar] = ta.y;
            As[ac + 2][ar] = ta.z; As[ac + 3][ar] = ta.w;
            const int br = vidx >> 5, bc = (vidx & 31) * 4;
            *(float4*)&Bs[br][bc] = *(const float4*)&Bb[(size_t)(k0 + br) * E_ + n0 + bc];
        }
        __syncthreads();
        #pragma unroll
        for (int kk = 0; kk < 16; kk++) {
            float a[8], bb[8];
            *(float4*)&a[0]  = *(const float4*)&As[kk][ty * 4];
            *(float4*)&a[4]  = *(const float4*)&As[kk][64 + ty * 4];
            *(float4*)&bb[0] = *(const float4*)&Bs[kk][tx * 4];
            *(float4*)&bb[4] = *(const float4*)&Bs[kk][64 + tx * 4];
            #pragma unroll
            for (int i = 0; i < 8; i++)
                #pragma unroll
                for (int j = 0; j < 8; j++)
                    acc[i][j] += a[i] * bb[j];
        }
        __syncthreads();
    }

    #pragma unroll
    for (int i = 0; i < 8; i++) {
        const int t = (i < 4) ? (ty * 4 + i) : (64 + ty * 4 + i - 4);
        const size_t rowbase = ((size_t)b * T_ + t) * E_;
        #pragma unroll
        for (int jh = 0; jh < 2; jh++) {
            const int c0 = n0 + jh * 64 + tx * 4;
            const float4 xr = *(const float4*)&X[rowbase + c0];
            float4 o;
            o.x = xr.x + acc[i][jh * 4 + 0];
            o.y = xr.y + acc[i][jh * 4 + 1];
            o.z = xr.z + acc[i][jh * 4 + 2];
            o.w = xr.w + acc[i][jh * 4 + 3];
            *(float4*)&O[rowbase + c0] = o;
        }
    }
}

// ---------------------------------------------------------------------------
// LayerNorm -> fp16 output
// ---------------------------------------------------------------------------
__global__ void ln_f16_kernel(const float* __restrict__ X,
                              const float* __restrict__ g,
                              const float* __restrict__ b,
                              __half* __restrict__ Ohi)
{
    const int row = blockIdx.x;
    const int tid = threadIdx.x;
    const int lane = tid & 31, wid = tid >> 5;

    const float4 v = ((const float4*)(X + (size_t)row * E_))[tid];
    float s  = v.x + v.y + v.z + v.w;
    float sq = v.x * v.x + v.y * v.y + v.z * v.z + v.w * v.w;

    #pragma unroll
    for (int off = 16; off > 0; off >>= 1) {
        s  += __shfl_xor_sync(0xffffffffu, s,  off);
        sq += __shfl_xor_sync(0xffffffffu, sq, off);
    }
    __shared__ float ss[4], ssq[4];
    if (lane == 0) { ss[wid] = s; ssq[wid] = sq; }
    __syncthreads();
    s  = ss[0]  + ss[1]  + ss[2]  + ss[3];
    sq = ssq[0] + ssq[1] + ssq[2] + ssq[3];

    const float mean = s * (1.0f / E_);
    const float var  = sq * (1.0f / E_) - mean * mean;
    const float inv  = rsqrtf(var + 1e-5f);

    const float4 gg = ((const float4*)g)[tid];
    const float4 bb = ((const float4*)b)[tid];
    const float o0 = (v.x - mean) * inv * gg.x + bb.x;
    const float o1 = (v.y - mean) * inv * gg.y + bb.y;
    const float o2 = (v.z - mean) * inv * gg.z + bb.z;
    const float o3 = (v.w - mean) * inv * gg.w + bb.w;

    __half2* ph = (__half2*)(Ohi + (size_t)row * E_);
    ph[tid * 2 + 0] = __halves2half2(__float2half_rn(o0), __float2half_rn(o1));
    ph[tid * 2 + 1] = __halves2half2(__float2half_rn(o2), __float2half_rn(o3));
}

// ---------------------------------------------------------------------------
// Merged transpose (fp32 -> fp16) for all 5 weights in ONE launch.
// ---------------------------------------------------------------------------
__global__ void transpose_all(
    const float* __restrict__ wq, const float* __restrict__ wk,
    const float* __restrict__ wv, const float* __restrict__ w1,
    const float* __restrict__ w2,
    __half* __restrict__ qt, __half* __restrict__ kt,
    __half* __restrict__ vt, __half* __restrict__ o1t,
    __half* __restrict__ o2t)
{
    __shared__ float tile[32][33];
    const int bid = blockIdx.x;
    const float* W; __half* Th;
    int Kdim, Ndim, t;
    if (bid < 768) {
        t = bid & 255; Kdim = E_; Ndim = E_;
        if (bid < 256)      { W = wq; Th = qt; }
        else if (bid < 512) { W = wk; Th = kt; }
        else                { W = wv; Th = vt; }
    } else if (bid < 1792) {
        t = bid - 768; Kdim = E_; Ndim = FF_;
        W = w1; Th = o1t;
    } else {
        t = bid - 1792; Kdim = FF_; Ndim = E_;
        W = w2; Th = o2t;
    }
    const int nblocks = Ndim / 32;
    const int n0 = (t % nblocks) * 32, k0 = (t / nblocks) * 32;
    const int tx = threadIdx.x, ty = threadIdx.y;   // (32, 8)
    #pragma unroll
    for (int i = 0; i < 4; ++i)
        tile[ty + i * 8][tx] = W[(size_t)(k0 + ty + i * 8) * Ndim + n0 + tx];
    __syncthreads();
    #pragma unroll
    for (int i = 0; i < 4; ++i) {
        const float v = tile[tx][ty + i * 8];
        const size_t o = (size_t)(n0 + ty + i * 8) * Kdim + k0 + tx;
        Th[o] = __float2half_rn(v);
    }
}

// ---------------------------------------------------------------------------
// Launch
// ---------------------------------------------------------------------------
extern "C" void kernel_launch(void* const* d_in, const int* in_sizes, int n_in,
                              void* d_out, int out_size)
{
    const float* x   = (const float*)d_in[0];
    const float* wq  = (const float*)d_in[1];
    const float* bq  = (const float*)d_in[2];
    const float* wk  = (const float*)d_in[3];
    const float* bk  = (const float*)d_in[4];
    const float* wv  = (const float*)d_in[5];
    const float* bv  = (const float*)d_in[6];
    const float* g1  = (const float*)d_in[7];
    const float* b1  = (const float*)d_in[8];
    const float* g2  = (const float*)d_in[9];
    const float* b2  = (const float*)d_in[10];
    const float* w1  = (const float*)d_in[11];
    const float* bm1 = (const float*)d_in[12];
    const float* w2  = (const float*)d_in[13];
    const float* bm2 = (const float*)d_in[14];
    float* out = (float*)d_out;

    __half *h_hi, *h2_hi, *m1_hi;
    __half *wqt, *wkt, *wvt, *w1t, *w2t;
    float *q, *k, *v, *att;
    cudaGetSymbolAddress((void**)&h_hi,  g_h_hi);
    cudaGetSymbolAddress((void**)&h2_hi, g_h2_hi);
    cudaGetSymbolAddress((void**)&m1_hi, g_m1_hi);
    cudaGetSymbolAddress((void**)&wqt, g_wqt);
    cudaGetSymbolAddress((void**)&wkt, g_wkt);
    cudaGetSymbolAddress((void**)&wvt, g_wvt);
    cudaGetSymbolAddress((void**)&w1t, g_w1t);
    cudaGetSymbolAddress((void**)&w2t, g_w2t);
    cudaGetSymbolAddress((void**)&q, g_q); cudaGetSymbolAddress((void**)&k, g_k);
    cudaGetSymbolAddress((void**)&v, g_v); cudaGetSymbolAddress((void**)&att, g_att);

    cudaFuncSetAttribute(gemm_mma_kernel<0, 0>, cudaFuncAttributeMaxDynamicSharedMemorySize, GEMM_SMEM_BYTES);
    cudaFuncSetAttribute(gemm_mma_kernel<1, 1>, cudaFuncAttributeMaxDynamicSharedMemorySize, GEMM_SMEM_BYTES);

    transpose_all<<<2816, dim3(32, 8)>>>(wq, wk, wv, w1, w2, wqt, wkt, wvt, w1t, w2t);

    ln_f16_kernel<<<ROWS, 128>>>(x, g1, b1, h_hi);

    const dim3 gQKV(E_ / GBN, ROWS / GBM);     // (4, 512)
    gemm_mma_kernel<0, 0><<<gQKV, 256, GEMM_SMEM_BYTES>>>(h_hi, wqt, bq, nullptr, q, nullptr, E_, E_);
    gemm_mma_kernel<0, 0><<<gQKV, 256, GEMM_SMEM_BYTES>>>(h_hi, wkt, bk, nullptr, k, nullptr, E_, E_);
    gemm_mma_kernel<0, 0><<<gQKV, 256, GEMM_SMEM_BYTES>>>(h_hi, wvt, bv, nullptr, v, nullptr, E_, E_);

    qk_softmax_kernel<<<B_, 256>>>(q, k, att);
    pv_kernel<<<dim3(E_ / 128, B_), 256>>>(att, v, x, out);

    ln_f16_kernel<<<ROWS, 128>>>(out, g2, b2, h2_hi);

    gemm_mma_kernel<1, 1><<<dim3(FF_ / GBN, ROWS / GBM), 256, GEMM_SMEM_BYTES>>>(
        h2_hi, w1t, bm1, nullptr, nullptr, m1_hi, FF_, E_);

    gemm_mma_kernel<0, 0><<<dim3(E_ / GBN, ROWS / GBM), 256, GEMM_SMEM_BYTES>>>(
        m1_hi, w2t, bm2, out, out, nullptr, E_, FF_);
}

// round 13
// speedup vs baseline: 1.1841x; 1.0806x over previous
#include <cuda_runtime.h>
#include <cuda_fp16.h>
#include <math.h>
#include <stdint.h>

// ---------------------------------------------------------------------------
// Shape (fixed): B=512, T=128, E=512, FF=2048
// ---------------------------------------------------------------------------
#define B_   512
#define T_   128
#define E_   512
#define FF_  2048
#define ROWS (B_ * T_)          // 65536

// ---------------------------------------------------------------------------
// Scratch (device globals)
// ---------------------------------------------------------------------------
__device__ __half g_h_hi [ROWS * E_];
__device__ __half g_h2_hi[ROWS * E_];
__device__ __half g_m1_hi[ROWS * FF_];
__device__ __half g_qh[ROWS * E_], g_kh[ROWS * E_];
__device__ float  g_v [ROWS * E_];
__device__ float  g_att[B_ * T_ * T_];
__device__ __half g_wqt[E_ * E_];
__device__ __half g_wkt[E_ * E_];
__device__ __half g_wvt[E_ * E_];
__device__ __half g_w1t[FF_ * E_];
__device__ __half g_w2t[E_ * FF_];

// ---------------------------------------------------------------------------
// Baseline-PTX helpers
// ---------------------------------------------------------------------------
__device__ __forceinline__ uint32_t smem_u32(const void* p) {
    uint32_t a;
    asm("{ .reg .u64 t; cvta.to.shared.u64 t, %1; cvt.u32.u64 %0, t; }"
        : "=r"(a) : "l"(p));
    return a;
}
__device__ __forceinline__ void cp_async16(uint32_t dst, const void* src) {
    asm volatile("cp.async.cg.shared.global [%0], [%1], 16;" :: "r"(dst), "l"(src));
}
__device__ __forceinline__ void cp_commit() {
    asm volatile("cp.async.commit_group;" ::: "memory");
}
__device__ __forceinline__ void cp_wait0() {
    asm volatile("cp.async.wait_group 0;" ::: "memory");
}
__device__ __forceinline__ void cp_wait1() {
    asm volatile("cp.async.wait_group 1;" ::: "memory");
}
__device__ __forceinline__ void cp_wait2() {
    asm volatile("cp.async.wait_group 2;" ::: "memory");
}

#define LDSM_X4(r, addr) \
    asm volatile("ldmatrix.sync.aligned.m8n8.x4.shared.b16 {%0,%1,%2,%3}, [%4];" \
        : "=r"((r)[0]), "=r"((r)[1]), "=r"((r)[2]), "=r"((r)[3]) : "r"(addr))

__device__ __forceinline__ void mma16816(float* c, const uint32_t* a,
                                         uint32_t b0, uint32_t b1) {
    asm volatile(
        "mma.sync.aligned.m16n8k16.row.col.f32.f16.f16.f32 "
        "{%0,%1,%2,%3}, {%4,%5,%6,%7}, {%8,%9}, {%0,%1,%2,%3};"
        : "+f"(c[0]), "+f"(c[1]), "+f"(c[2]), "+f"(c[3])
        : "r"(a[0]), "r"(a[1]), "r"(a[2]), "r"(a[3]), "r"(b0), "r"(b1));
}

__device__ __forceinline__ float gelu_exact(float x) {
    return 0.5f * x * (1.0f + erff(x * 0.7071067811865476f));
}

// ---------------------------------------------------------------------------
// HMMA GEMM, 256 threads (8 warps 4x2), warp tile 32x64, occupancy 2.
// BM=128, BN=128, BK=64, pure fp16, 3-stage cp.async pipeline.
// Stage segs (halves): A @0 | B @9216 ; stage = 18432 halves (36KB); 3 stages.
// ---------------------------------------------------------------------------
#define GBM 128
#define GBN 128
#define GSTRIDE 72
#define SEG_HALVES 9216                       // 128*72
#define STAGE_HALVES 18432                    // 2*9216
static constexpr int GEMM_SMEM_BYTES = 3 * STAGE_HALVES * 2;  // 110592

template<int ACT, int OUTM>
__global__ __launch_bounds__(256, 2)
void gemm_mma_kernel(const __half* __restrict__ A,
                     const __half* __restrict__ B,
                     const float* __restrict__ bias, const float* __restrict__ res,
                     float* __restrict__ Cf, __half* __restrict__ Chi,
                     int Ntot, int K)
{
    extern __shared__ __half sm[];
    const int tid = threadIdx.x, wid = tid >> 5, lane = tid & 31;
    const int m0 = blockIdx.y * GBM;
    const int n0 = blockIdx.x * GBN;
    const uint32_t smb = smem_u32(sm);

    const __half* ptrA = A + (size_t)m0 * K;
    const __half* ptrB = B + (size_t)n0 * K;

    auto load_stage = [&](int st, int k0) {
        const uint32_t base = smb + (uint32_t)st * (STAGE_HALVES * 2);
        #pragma unroll
        for (int it = 0; it < 8; ++it) {
            const int i = tid + it * 256;            // 0..2047
            const int seg = i >> 10;                 // 0 A, 1 B
            const int j = i & 1023;
            const int row = j >> 3, ch = j & 7;
            const __half* src = (seg == 0 ? ptrA : ptrB) + (size_t)row * K + k0 + ch * 8;
            const uint32_t dst = base + (uint32_t)((seg * SEG_HALVES + row * GSTRIDE + ch * 8) * 2);
            cp_async16(dst, src);
        }
    };

    float acc[2][8][4];
    #pragma unroll
    for (int mt = 0; mt < 2; ++mt)
        #pragma unroll
        for (int nt = 0; nt < 8; ++nt)
            #pragma unroll
            for (int e = 0; e < 4; ++e) acc[mt][nt][e] = 0.0f;

    const int wm = (wid >> 1) * 32;
    const int wn = (wid & 1) * 64;
    const int NC = K >> 6;

    load_stage(0, 0);  cp_commit();
    load_stage(1, 64); cp_commit();

    for (int c = 0; c < NC; ++c) {
        if (c + 2 < NC) load_stage((c + 2) % 3, (c + 2) * 64);
        cp_commit();
        cp_wait2();
        __syncthreads();

        const uint32_t sb = smb + (uint32_t)(c % 3) * (STAGE_HALVES * 2);
        #pragma unroll
        for (int kk = 0; kk < 64; kk += 16) {
            uint32_t bh[8][2];
            #pragma unroll
            for (int ng = 0; ng < 4; ++ng) {
                const uint32_t addr = sb +
                    (uint32_t)((SEG_HALVES + (wn + ng * 16 + (lane & 15)) * GSTRIDE
                                + kk + ((lane >> 4) << 3)) << 1);
                uint32_t r[4];
                LDSM_X4(r, addr);
                bh[2 * ng][0] = r[0]; bh[2 * ng][1] = r[2];
                bh[2 * ng + 1][0] = r[1]; bh[2 * ng + 1][1] = r[3];
            }
            uint32_t ah[2][4];
            #pragma unroll
            for (int mt = 0; mt < 2; ++mt) {
                const uint32_t addr = sb +
                    (uint32_t)(((wm + mt * 16 + (lane & 15)) * GSTRIDE
                                + kk + ((lane >> 4) << 3)) << 1);
                LDSM_X4(ah[mt], addr);
            }
            #pragma unroll
            for (int mt = 0; mt < 2; ++mt)
                #pragma unroll
                for (int nt = 0; nt < 8; ++nt)
                    mma16816(acc[mt][nt], ah[mt], bh[nt][0], bh[nt][1]);
        }
        __syncthreads();
    }

    // epilogue
    #pragma unroll
    for (int mt = 0; mt < 2; ++mt) {
        const int r0 = m0 + wm + mt * 16 + (lane >> 2);
        const int r1 = r0 + 8;
        #pragma unroll
        for (int nt = 0; nt < 8; ++nt) {
            const int col = n0 + wn + nt * 8 + (lane & 3) * 2;
            const float bia0 = __ldg(&bias[col]);
            const float bia1 = __ldg(&bias[col + 1]);
            float v00 = acc[mt][nt][0] + bia0;
            float v01 = acc[mt][nt][1] + bia1;
            float v10 = acc[mt][nt][2] + bia0;
            float v11 = acc[mt][nt][3] + bia1;
            if (ACT == 1) {
                v00 = gelu_exact(v00); v01 = gelu_exact(v01);
                v10 = gelu_exact(v10); v11 = gelu_exact(v11);
            }
            if (OUTM == 0) {
                if (res) {
                    const float2 q0 = *(const float2*)(res + (size_t)r0 * Ntot + col);
                    const float2 q1 = *(const float2*)(res + (size_t)r1 * Ntot + col);
                    v00 += q0.x; v01 += q0.y; v10 += q1.x; v11 += q1.y;
                }
                *(float2*)(Cf + (size_t)r0 * Ntot + col) = make_float2(v00, v01);
                *(float2*)(Cf + (size_t)r1 * Ntot + col) = make_float2(v10, v11);
            } else {
                *(__half2*)(Chi + (size_t)r0 * Ntot + col) =
                    __halves2half2(__float2half_rn(v00), __float2half_rn(v01));
                *(__half2*)(Chi + (size_t)r1 * Ntot + col) =
                    __halves2half2(__float2half_rn(v10), __float2half_rn(v11));
            }
        }
    }
}

// ---------------------------------------------------------------------------
// HMMA QK^T + scale + causal mask + softmax. One block per batch (S = 128x128).
// Mainloop = R7-proven 32x64 warp-tile pattern (BK=32, stride 40, occ 2).
// Softmax in the C-fragment register mapping (validated by GEMM epilogues).
// P (normalized, fp32) written row-major to global for pv_kernel.
// ---------------------------------------------------------------------------
#define QKSTRIDE 40
#define QK_SEG   5120                         // 128*40
#define QK_STAGE 10240                        // 2*5120
static constexpr int QK_SMEM_BYTES = 2 * QK_STAGE * 2;  // 40960

__global__ __launch_bounds__(256, 2)
void qk_mma_softmax_kernel(const __half* __restrict__ Q, const __half* __restrict__ Kh,
                           float* __restrict__ P)
{
    extern __shared__ __half sm[];
    __shared__ float redmax[2][128];
    __shared__ float redsum[2][128];

    const int b = blockIdx.x;
    const int tid = threadIdx.x, wid = tid >> 5, lane = tid & 31;
    const uint32_t smb = smem_u32(sm);
    const size_t base = (size_t)b * T_ * E_;
    const __half* ptrA = Q  + base;
    const __half* ptrB = Kh + base;

    auto load_stage = [&](int st, int k0) {
        const uint32_t sbase = smb + (uint32_t)st * (QK_STAGE * 2);
        #pragma unroll
        for (int it = 0; it < 4; ++it) {
            const int i = tid + it * 256;            // 0..1023
            const int seg = i >> 9;                  // 0 Q, 1 K
            const int j = i & 511;
            const int row = j >> 2, ch = j & 3;
            const __half* src = (seg == 0 ? ptrA : ptrB) + (size_t)row * E_ + k0 + ch * 8;
            const uint32_t dst = sbase + (uint32_t)((seg * QK_SEG + row * QKSTRIDE + ch * 8) * 2);
            cp_async16(dst, src);
        }
    };

    float acc[2][8][4];
    #pragma unroll
    for (int mt = 0; mt < 2; ++mt)
        #pragma unroll
        for (int nt = 0; nt < 8; ++nt)
            #pragma unroll
            for (int e = 0; e < 4; ++e) acc[mt][nt][e] = 0.0f;

    const int wm = (wid >> 1) * 32;
    const int wn = (wid & 1) * 64;
    const int NC = E_ >> 5;   // 16

    load_stage(0, 0);
    cp_commit();

    for (int c = 0; c < NC; ++c) {
        if (c + 1 < NC) {
            load_stage((c + 1) & 1, (c + 1) * 32);
            cp_commit();
            cp_wait1();
        } else {
            cp_wait0();
        }
        __syncthreads();

        const uint32_t sb = smb + (uint32_t)(c & 1) * (QK_STAGE * 2);
        #pragma unroll
        for (int kk = 0; kk < 32; kk += 16) {
            uint32_t bh[8][2];
            #pragma unroll
            for (int ng = 0; ng < 4; ++ng) {
                const uint32_t addr = sb +
                    (uint32_t)((QK_SEG + (wn + ng * 16 + (lane & 15)) * QKSTRIDE
                                + kk + ((lane >> 4) << 3)) << 1);
                uint32_t r[4];
                LDSM_X4(r, addr);
                bh[2 * ng][0] = r[0]; bh[2 * ng][1] = r[2];
                bh[2 * ng + 1][0] = r[1]; bh[2 * ng + 1][1] = r[3];
            }
            uint32_t ah[2][4];
            #pragma unroll
            for (int mt = 0; mt < 2; ++mt) {
                const uint32_t addr = sb +
                    (uint32_t)(((wm + mt * 16 + (lane & 15)) * QKSTRIDE
                                + kk + ((lane >> 4) << 3)) << 1);
                LDSM_X4(ah[mt], addr);
            }
            #pragma unroll
            for (int mt = 0; mt < 2; ++mt)
                #pragma unroll
                for (int nt = 0; nt < 8; ++nt)
                    mma16816(acc[mt][nt], ah[mt], bh[nt][0], bh[nt][1]);
        }
        __syncthreads();
    }

    // ---- scale + causal mask + row max (per-warp over its 64 cols) ----
    float pm[2][2];
    #pragma unroll
    for (int mt = 0; mt < 2; ++mt) { pm[mt][0] = -INFINITY; pm[mt][1] = -INFINITY; }
    #pragma unroll
    for (int mt = 0; mt < 2; ++mt)
        #pragma unroll
        for (int nt = 0; nt < 8; ++nt)
            #pragma unroll
            for (int e = 0; e < 4; ++e) {
                const int r = wm + mt * 16 + (lane >> 2) + (e >> 1) * 8;
                const int c = wn + nt * 8 + (lane & 3) * 2 + (e & 1);
                float v = acc[mt][nt][e] * 0.125f;   // 1/sqrt(64)
                if (c > r) v = -INFINITY;
                acc[mt][nt][e] = v;
                pm[mt][e >> 1] = fmaxf(pm[mt][e >> 1], v);
            }
    #pragma unroll
    for (int mt = 0; mt < 2; ++mt)
        #pragma unroll
        for (int rh = 0; rh < 2; ++rh) {
            pm[mt][rh] = fmaxf(pm[mt][rh], __shfl_xor_sync(0xffffffffu, pm[mt][rh], 1));
            pm[mt][rh] = fmaxf(pm[mt][rh], __shfl_xor_sync(0xffffffffu, pm[mt][rh], 2));
        }
    if ((lane & 3) == 0) {
        #pragma unroll
        for (int mt = 0; mt < 2; ++mt)
            #pragma unroll
            for (int rh = 0; rh < 2; ++rh)
                redmax[wid & 1][wm + mt * 16 + (lane >> 2) + rh * 8] = pm[mt][rh];
    }
    __syncthreads();

    // ---- exp + row sum ----
    float ps[2][2] = {{0.0f, 0.0f}, {0.0f, 0.0f}};
    float mrow[2][2];
    #pragma unroll
    for (int mt = 0; mt < 2; ++mt)
        #pragma unroll
        for (int rh = 0; rh < 2; ++rh) {
            const int r = wm + mt * 16 + (lane >> 2) + rh * 8;
            mrow[mt][rh] = fmaxf(redmax[0][r], redmax[1][r]);
        }
    #pragma unroll
    for (int mt = 0; mt < 2; ++mt)
        #pragma unroll
        for (int nt = 0; nt < 8; ++nt)
            #pragma unroll
            for (int e = 0; e < 4; ++e) {
                const float p = expf(acc[mt][nt][e] - mrow[mt][e >> 1]);
                acc[mt][nt][e] = p;
                ps[mt][e >> 1] += p;
            }
    #pragma unroll
    for (int mt = 0; mt < 2; ++mt)
        #pragma unroll
        for (int rh = 0; rh < 2; ++rh) {
            ps[mt][rh] += __shfl_xor_sync(0xffffffffu, ps[mt][rh], 1);
            ps[mt][rh] += __shfl_xor_sync(0xffffffffu, ps[mt][rh], 2);
        }
    if ((lane & 3) == 0) {
        #pragma unroll
        for (int mt = 0; mt < 2; ++mt)
            #pragma unroll
            for (int rh = 0; rh < 2; ++rh)
                redsum[wid & 1][wm + mt * 16 + (lane >> 2) + rh * 8] = ps[mt][rh];
    }
    __syncthreads();

    // ---- normalize + store P (fp32, row-major) ----
    float* Pb = P + (size_t)b * T_ * T_;
    #pragma unroll
    for (int mt = 0; mt < 2; ++mt)
        #pragma unroll
        for (int rh = 0; rh < 2; ++rh) {
            const int r = wm + mt * 16 + (lane >> 2) + rh * 8;
            const float inv = 1.0f / (redsum[0][r] + redsum[1][r]);
            #pragma unroll
            for (int nt = 0; nt < 8; ++nt) {
                const int c = wn + nt * 8 + (lane & 3) * 2;
                *(float2*)(Pb + (size_t)r * T_ + c) =
                    make_float2(acc[mt][nt][rh * 2 + 0] * inv,
                                acc[mt][nt][rh * 2 + 1] * inv);
            }
        }
}

// ---------------------------------------------------------------------------
// O = X + P @ V (batched). grid=(4, 512). (R1-validated)
// ---------------------------------------------------------------------------
__global__ __launch_bounds__(256, 2)
void pv_kernel(const float* __restrict__ P, const float* __restrict__ V,
               const float* __restrict__ X, float* __restrict__ O)
{
    const int b  = blockIdx.y;
    const int n0 = blockIdx.x * 128;
    const float* Ab = P + (size_t)b * T_ * T_;
    const float* Bb = V + (size_t)b * T_ * E_;

    __shared__ float As[16][128];
    __shared__ float Bs[16][128];
    const int tid = threadIdx.x;
    const int tx = tid & 15, ty = tid >> 4;

    float acc[8][8];
    #pragma unroll
    for (int i = 0; i < 8; i++)
        #pragma unroll
        for (int j = 0; j < 8; j++) acc[i][j] = 0.0f;

    for (int k0 = 0; k0 < T_; k0 += 16) {
        #pragma unroll
        for (int l = 0; l < 2; l++) {
            const int vidx = tid + l * 256;
            const int ar = vidx >> 2, ac = (vidx & 3) * 4;
            const float4 ta = *(const float4*)&Ab[(size_t)ar * T_ + k0 + ac];
            As[ac + 0][ar] = ta.x; As[ac + 1][ar] = ta.y;
            As[ac + 2][ar] = ta.z; As[ac + 3][ar] = ta.w;
            const int br = vidx >> 5, bc = (vidx & 31) * 4;
            *(float4*)&Bs[br][bc] = *(const float4*)&Bb[(size_t)(k0 + br) * E_ + n0 + bc];
        }
        __syncthreads();
        #pragma unroll
        for (int kk = 0; kk < 16; kk++) {
            float a[8], bb[8];
            *(float4*)&a[0]  = *(const float4*)&As[kk][ty * 4];
            *(float4*)&a[4]  = *(const float4*)&As[kk][64 + ty * 4];
            *(float4*)&bb[0] = *(const float4*)&Bs[kk][tx * 4];
            *(float4*)&bb[4] = *(const float4*)&Bs[kk][64 + tx * 4];
            #pragma unroll
            for (int i = 0; i < 8; i++)
                #pragma unroll
                for (int j = 0; j < 8; j++)
                    acc[i][j] += a[i] * bb[j];
        }
        __syncthreads();
    }

    #pragma unroll
    for (int i = 0; i < 8; i++) {
        const int t = (i < 4) ? (ty * 4 + i) : (64 + ty * 4 + i - 4);
        const size_t rowbase = ((size_t)b * T_ + t) * E_;
        #pragma unroll
        for (int jh = 0; jh < 2; jh++) {
            const int c0 = n0 + jh * 64 + tx * 4;
            const float4 xr = *(const float4*)&X[rowbase + c0];
            float4 o;
            o.x = xr.x + acc[i][jh * 4 + 0];
            o.y = xr.y + acc[i][jh * 4 + 1];
            o.z = xr.z + acc[i][jh * 4 + 2];
            o.w = xr.w + acc[i][jh * 4 + 3];
            *(float4*)&O[rowbase + c0] = o;
        }
    }
}

// ---------------------------------------------------------------------------
// LayerNorm -> fp16 output
// ---------------------------------------------------------------------------
__global__ void ln_f16_kernel(const float* __restrict__ X,
                              const float* __restrict__ g,
                              const float* __restrict__ b,
                              __half* __restrict__ Ohi)
{
    const int row = blockIdx.x;
    const int tid = threadIdx.x;
    const int lane = tid & 31, wid = tid >> 5;

    const float4 v = ((const float4*)(X + (size_t)row * E_))[tid];
    float s  = v.x + v.y + v.z + v.w;
    float sq = v.x * v.x + v.y * v.y + v.z * v.z + v.w * v.w;

    #pragma unroll
    for (int off = 16; off > 0; off >>= 1) {
        s  += __shfl_xor_sync(0xffffffffu, s,  off);
        sq += __shfl_xor_sync(0xffffffffu, sq, off);
    }
    __shared__ float ss[4], ssq[4];
    if (lane == 0) { ss[wid] = s; ssq[wid] = sq; }
    __syncthreads();
    s  = ss[0]  + ss[1]  + ss[2]  + ss[3];
    sq = ssq[0] + ssq[1] + ssq[2] + ssq[3];

    const float mean = s * (1.0f / E_);
    const float var  = sq * (1.0f / E_) - mean * mean;
    const float inv  = rsqrtf(var + 1e-5f);

    const float4 gg = ((const float4*)g)[tid];
    const float4 bb = ((const float4*)b)[tid];
    const float o0 = (v.x - mean) * inv * gg.x + bb.x;
    const float o1 = (v.y - mean) * inv * gg.y + bb.y;
    const float o2 = (v.z - mean) * inv * gg.z + bb.z;
    const float o3 = (v.w - mean) * inv * gg.w + bb.w;

    __half2* ph = (__half2*)(Ohi + (size_t)row * E_);
    ph[tid * 2 + 0] = __halves2half2(__float2half_rn(o0), __float2half_rn(o1));
    ph[tid * 2 + 1] = __halves2half2(__float2half_rn(o2), __float2half_rn(o3));
}

// ---------------------------------------------------------------------------
// Merged transpose (fp32 -> fp16) for all 5 weights in ONE launch.
// ---------------------------------------------------------------------------
__global__ void transpose_all(
    const float* __restrict__ wq, const float* __restrict__ wk,
    const float* __restrict__ wv, const float* __restrict__ w1,
    const float* __restrict__ w2,
    __half* __restrict__ qt, __half* __restrict__ kt,
    __half* __restrict__ vt, __half* __restrict__ o1t,
    __half* __restrict__ o2t)
{
    __shared__ float tile[32][33];
    const int bid = blockIdx.x;
    const float* W; __half* Th;
    int Kdim, Ndim, t;
    if (bid < 768) {
        t = bid & 255; Kdim = E_; Ndim = E_;
        if (bid < 256)      { W = wq; Th = qt; }
        else if (bid < 512) { W = wk; Th = kt; }
        else                { W = wv; Th = vt; }
    } else if (bid < 1792) {
        t = bid - 768; Kdim = E_; Ndim = FF_;
        W = w1; Th = o1t;
    } else {
        t = bid - 1792; Kdim = FF_; Ndim = E_;
        W = w2; Th = o2t;
    }
    const int nblocks = Ndim / 32;
    const int n0 = (t % nblocks) * 32, k0 = (t / nblocks) * 32;
    const int tx = threadIdx.x, ty = threadIdx.y;   // (32, 8)
    #pragma unroll
    for (int i = 0; i < 4; ++i)
        tile[ty + i * 8][tx] = W[(size_t)(k0 + ty + i * 8) * Ndim + n0 + tx];
    __syncthreads();
    #pragma unroll
    for (int i = 0; i < 4; ++i) {
        const float v = tile[tx][ty + i * 8];
        const size_t o = (size_t)(n0 + ty + i * 8) * Kdim + k0 + tx;
        Th[o] = __float2half_rn(v);
    }
}

// ---------------------------------------------------------------------------
// Launch
// ---------------------------------------------------------------------------
extern "C" void kernel_launch(void* const* d_in, const int* in_sizes, int n_in,
                              void* d_out, int out_size)
{
    const float* x   = (const float*)d_in[0];
    const float* wq  = (const float*)d_in[1];
    const float* bq  = (const float*)d_in[2];
    const float* wk  = (const float*)d_in[3];
    const float* bk  = (const float*)d_in[4];
    const float* wv  = (const float*)d_in[5];
    const float* bv  = (const float*)d_in[6];
    const float* g1  = (const float*)d_in[7];
    const float* b1  = (const float*)d_in[8];
    const float* g2  = (const float*)d_in[9];
    const float* b2  = (const float*)d_in[10];
    const float* w1  = (const float*)d_in[11];
    const float* bm1 = (const float*)d_in[12];
    const float* w2  = (const float*)d_in[13];
    const float* bm2 = (const float*)d_in[14];
    float* out = (float*)d_out;

    __half *h_hi, *h2_hi, *m1_hi, *qh, *kh;
    __half *wqt, *wkt, *wvt, *w1t, *w2t;
    float *v, *att;
    cudaGetSymbolAddress((void**)&h_hi,  g_h_hi);
    cudaGetSymbolAddress((void**)&h2_hi, g_h2_hi);
    cudaGetSymbolAddress((void**)&m1_hi, g_m1_hi);
    cudaGetSymbolAddress((void**)&qh, g_qh);
    cudaGetSymbolAddress((void**)&kh, g_kh);
    cudaGetSymbolAddress((void**)&wqt, g_wqt);
    cudaGetSymbolAddress((void**)&wkt, g_wkt);
    cudaGetSymbolAddress((void**)&wvt, g_wvt);
    cudaGetSymbolAddress((void**)&w1t, g_w1t);
    cudaGetSymbolAddress((void**)&w2t, g_w2t);
    cudaGetSymbolAddress((void**)&v, g_v);
    cudaGetSymbolAddress((void**)&att, g_att);

    cudaFuncSetAttribute(gemm_mma_kernel<0, 0>, cudaFuncAttributeMaxDynamicSharedMemorySize, GEMM_SMEM_BYTES);
    cudaFuncSetAttribute(gemm_mma_kernel<0, 1>, cudaFuncAttributeMaxDynamicSharedMemorySize, GEMM_SMEM_BYTES);
    cudaFuncSetAttribute(gemm_mma_kernel<1, 1>, cudaFuncAttributeMaxDynamicSharedMemorySize, GEMM_SMEM_BYTES);
    cudaFuncSetAttribute(qk_mma_softmax_kernel, cudaFuncAttributeMaxDynamicSharedMemorySize, QK_SMEM_BYTES);

    transpose_all<<<2816, dim3(32, 8)>>>(wq, wk, wv, w1, w2, wqt, wkt, wvt, w1t, w2t);

    ln_f16_kernel<<<ROWS, 128>>>(x, g1, b1, h_hi);

    const dim3 gQKV(E_ / GBN, ROWS / GBM);     // (4, 512)
    gemm_mma_kernel<0, 1><<<gQKV, 256, GEMM_SMEM_BYTES>>>(h_hi, wqt, bq, nullptr, nullptr, qh, E_, E_);
    gemm_mma_kernel<0, 1><<<gQKV, 256, GEMM_SMEM_BYTES>>>(h_hi, wkt, bk, nullptr, nullptr, kh, E_, E_);
    gemm_mma_kernel<0, 0><<<gQKV, 256, GEMM_SMEM_BYTES>>>(h_hi, wvt, bv, nullptr, v, nullptr, E_, E_);

    qk_mma_softmax_kernel<<<B_, 256, QK_SMEM_BYTES>>>(qh, kh, att);
    pv_kernel<<<dim3(E_ / 128, B_), 256>>>(att, v, x, out);

    ln_f16_kernel<<<ROWS, 128>>>(out, g2, b2, h2_hi);

    gemm_mma_kernel<1, 1><<<dim3(FF_ / GBN, ROWS / GBM), 256, GEMM_SMEM_BYTES>>>(
        h2_hi, w1t, bm1, nullptr, nullptr, m1_hi, FF_, E_);

    gemm_mma_kernel<0, 0><<<dim3(E_ / GBN, ROWS / GBM), 256, GEMM_SMEM_BYTES>>>(
        m1_hi, w2t, bm2, out, out, nullptr, E_, FF_);
}

// round 15
// speedup vs baseline: 1.2941x; 1.0929x over previous
#include <cuda_runtime.h>
#include <cuda_fp16.h>
#include <math.h>
#include <stdint.h>

// ---------------------------------------------------------------------------
// Shape (fixed): B=512, T=128, E=512, FF=2048
// ---------------------------------------------------------------------------
#define B_   512
#define T_   128
#define E_   512
#define FF_  2048
#define ROWS (B_ * T_)          // 65536

// ---------------------------------------------------------------------------
// Scratch (device globals)
// ---------------------------------------------------------------------------
__device__ __half g_h_hi [ROWS * E_];
__device__ __half g_h2_hi[ROWS * E_];
__device__ __half g_m1_hi[ROWS * FF_];
__device__ __half g_qh[ROWS * E_], g_kh[ROWS * E_], g_vh[ROWS * E_];
__device__ __half g_atth[B_ * T_ * T_];
__device__ __half g_wqt[E_ * E_];
__device__ __half g_wkt[E_ * E_];
__device__ __half g_wvt[E_ * E_];
__device__ __half g_w1t[FF_ * E_];
__device__ __half g_w2t[E_ * FF_];

// ---------------------------------------------------------------------------
// Baseline-PTX helpers
// ---------------------------------------------------------------------------
__device__ __forceinline__ uint32_t smem_u32(const void* p) {
    uint32_t a;
    asm("{ .reg .u64 t; cvta.to.shared.u64 t, %1; cvt.u32.u64 %0, t; }"
        : "=r"(a) : "l"(p));
    return a;
}
__device__ __forceinline__ void cp_async16(uint32_t dst, const void* src) {
    asm volatile("cp.async.cg.shared.global [%0], [%1], 16;" :: "r"(dst), "l"(src));
}
__device__ __forceinline__ void cp_commit() {
    asm volatile("cp.async.commit_group;" ::: "memory");
}
__device__ __forceinline__ void cp_wait0() {
    asm volatile("cp.async.wait_group 0;" ::: "memory");
}
__device__ __forceinline__ void cp_wait1() {
    asm volatile("cp.async.wait_group 1;" ::: "memory");
}
__device__ __forceinline__ void cp_wait2() {
    asm volatile("cp.async.wait_group 2;" ::: "memory");
}

#define LDSM_X4(r, addr) \
    asm volatile("ldmatrix.sync.aligned.m8n8.x4.shared.b16 {%0,%1,%2,%3}, [%4];" \
        : "=r"((r)[0]), "=r"((r)[1]), "=r"((r)[2]), "=r"((r)[3]) : "r"(addr))
#define LDSM_X4_T(r, addr) \
    asm volatile("ldmatrix.sync.aligned.m8n8.x4.trans.shared.b16 {%0,%1,%2,%3}, [%4];" \
        : "=r"((r)[0]), "=r"((r)[1]), "=r"((r)[2]), "=r"((r)[3]) : "r"(addr))

__device__ __forceinline__ void mma16816(float* c, const uint32_t* a,
                                         uint32_t b0, uint32_t b1) {
    asm volatile(
        "mma.sync.aligned.m16n8k16.row.col.f32.f16.f16.f32 "
        "{%0,%1,%2,%3}, {%4,%5,%6,%7}, {%8,%9}, {%0,%1,%2,%3};"
        : "+f"(c[0]), "+f"(c[1]), "+f"(c[2]), "+f"(c[3])
        : "r"(a[0]), "r"(a[1]), "r"(a[2]), "r"(a[3]), "r"(b0), "r"(b1));
}

__device__ __forceinline__ float gelu_exact(float x) {
    return 0.5f * x * (1.0f + erff(x * 0.7071067811865476f));
}

// ---------------------------------------------------------------------------
// HMMA GEMM, 256 threads (8 warps 4x2), warp tile 32x64, occupancy 2.
// BM=128, BN=128, BK=64, pure fp16, 3-stage cp.async pipeline. (R13-proven)
// ---------------------------------------------------------------------------
#define GBM 128
#define GBN 128
#define GSTRIDE 72
#define SEG_HALVES 9216                       // 128*72
#define STAGE_HALVES 18432                    // 2*9216
static constexpr int GEMM_SMEM_BYTES = 3 * STAGE_HALVES * 2;  // 110592

template<int ACT, int OUTM>
__global__ __launch_bounds__(256, 2)
void gemm_mma_kernel(const __half* __restrict__ A,
                     const __half* __restrict__ B,
                     const float* __restrict__ bias, const float* __restrict__ res,
                     float* __restrict__ Cf, __half* __restrict__ Chi,
                     int Ntot, int K)
{
    extern __shared__ __half sm[];
    const int tid = threadIdx.x, wid = tid >> 5, lane = tid & 31;
    const int m0 = blockIdx.y * GBM;
    const int n0 = blockIdx.x * GBN;
    const uint32_t smb = smem_u32(sm);

    const __half* ptrA = A + (size_t)m0 * K;
    const __half* ptrB = B + (size_t)n0 * K;

    auto load_stage = [&](int st, int k0) {
        const uint32_t base = smb + (uint32_t)st * (STAGE_HALVES * 2);
        #pragma unroll
        for (int it = 0; it < 8; ++it) {
            const int i = tid + it * 256;            // 0..2047
            const int seg = i >> 10;                 // 0 A, 1 B
            const int j = i & 1023;
            const int row = j >> 3, ch = j & 7;
            const __half* src = (seg == 0 ? ptrA : ptrB) + (size_t)row * K + k0 + ch * 8;
            const uint32_t dst = base + (uint32_t)((seg * SEG_HALVES + row * GSTRIDE + ch * 8) * 2);
            cp_async16(dst, src);
        }
    };

    float acc[2][8][4];
    #pragma unroll
    for (int mt = 0; mt < 2; ++mt)
        #pragma unroll
        for (int nt = 0; nt < 8; ++nt)
            #pragma unroll
            for (int e = 0; e < 4; ++e) acc[mt][nt][e] = 0.0f;

    const int wm = (wid >> 1) * 32;
    const int wn = (wid & 1) * 64;
    const int NC = K >> 6;

    load_stage(0, 0);  cp_commit();
    load_stage(1, 64); cp_commit();

    for (int c = 0; c < NC; ++c) {
        if (c + 2 < NC) load_stage((c + 2) % 3, (c + 2) * 64);
        cp_commit();
        cp_wait2();
        __syncthreads();

        const uint32_t sb = smb + (uint32_t)(c % 3) * (STAGE_HALVES * 2);
        #pragma unroll
        for (int kk = 0; kk < 64; kk += 16) {
            uint32_t bh[8][2];
            #pragma unroll
            for (int ng = 0; ng < 4; ++ng) {
                const uint32_t addr = sb +
                    (uint32_t)((SEG_HALVES + (wn + ng * 16 + (lane & 15)) * GSTRIDE
                                + kk + ((lane >> 4) << 3)) << 1);
                uint32_t r[4];
                LDSM_X4(r, addr);
                bh[2 * ng][0] = r[0]; bh[2 * ng][1] = r[2];
                bh[2 * ng + 1][0] = r[1]; bh[2 * ng + 1][1] = r[3];
            }
            uint32_t ah[2][4];
            #pragma unroll
            for (int mt = 0; mt < 2; ++mt) {
                const uint32_t addr = sb +
                    (uint32_t)(((wm + mt * 16 + (lane & 15)) * GSTRIDE
                                + kk + ((lane >> 4) << 3)) << 1);
                LDSM_X4(ah[mt], addr);
            }
            #pragma unroll
            for (int mt = 0; mt < 2; ++mt)
                #pragma unroll
                for (int nt = 0; nt < 8; ++nt)
                    mma16816(acc[mt][nt], ah[mt], bh[nt][0], bh[nt][1]);
        }
        __syncthreads();
    }

    // epilogue
    #pragma unroll
    for (int mt = 0; mt < 2; ++mt) {
        const int r0 = m0 + wm + mt * 16 + (lane >> 2);
        const int r1 = r0 + 8;
        #pragma unroll
        for (int nt = 0; nt < 8; ++nt) {
            const int col = n0 + wn + nt * 8 + (lane & 3) * 2;
            const float bia0 = __ldg(&bias[col]);
            const float bia1 = __ldg(&bias[col + 1]);
            float v00 = acc[mt][nt][0] + bia0;
            float v01 = acc[mt][nt][1] + bia1;
            float v10 = acc[mt][nt][2] + bia0;
            float v11 = acc[mt][nt][3] + bia1;
            if (ACT == 1) {
                v00 = gelu_exact(v00); v01 = gelu_exact(v01);
                v10 = gelu_exact(v10); v11 = gelu_exact(v11);
            }
            if (OUTM == 0) {
                if (res) {
                    const float2 q0 = *(const float2*)(res + (size_t)r0 * Ntot + col);
                    const float2 q1 = *(const float2*)(res + (size_t)r1 * Ntot + col);
                    v00 += q0.x; v01 += q0.y; v10 += q1.x; v11 += q1.y;
                }
                *(float2*)(Cf + (size_t)r0 * Ntot + col) = make_float2(v00, v01);
                *(float2*)(Cf + (size_t)r1 * Ntot + col) = make_float2(v10, v11);
            } else {
                *(__half2*)(Chi + (size_t)r0 * Ntot + col) =
                    __halves2half2(__float2half_rn(v00), __float2half_rn(v01));
                *(__half2*)(Chi + (size_t)r1 * Ntot + col) =
                    __halves2half2(__float2half_rn(v10), __float2half_rn(v11));
            }
        }
    }
}

// ---------------------------------------------------------------------------
// HMMA QK^T + scale + mask + softmax (R13-validated). P output fp16.
// ---------------------------------------------------------------------------
#define QKSTRIDE 40
#define QK_SEG   5120
#define QK_STAGE 10240
static constexpr int QK_SMEM_BYTES = 2 * QK_STAGE * 2;  // 40960

__global__ __launch_bounds__(256, 2)
void qk_mma_softmax_kernel(const __half* __restrict__ Q, const __half* __restrict__ Kh,
                           __half* __restrict__ P)
{
    extern __shared__ __half sm[];
    __shared__ float redmax[2][128];
    __shared__ float redsum[2][128];

    const int b = blockIdx.x;
    const int tid = threadIdx.x, wid = tid >> 5, lane = tid & 31;
    const uint32_t smb = smem_u32(sm);
    const size_t base = (size_t)b * T_ * E_;
    const __half* ptrA = Q  + base;
    const __half* ptrB = Kh + base;

    auto load_stage = [&](int st, int k0) {
        const uint32_t sbase = smb + (uint32_t)st * (QK_STAGE * 2);
        #pragma unroll
        for (int it = 0; it < 4; ++it) {
            const int i = tid + it * 256;
            const int seg = i >> 9;
            const int j = i & 511;
            const int row = j >> 2, ch = j & 3;
            const __half* src = (seg == 0 ? ptrA : ptrB) + (size_t)row * E_ + k0 + ch * 8;
            const uint32_t dst = sbase + (uint32_t)((seg * QK_SEG + row * QKSTRIDE + ch * 8) * 2);
            cp_async16(dst, src);
        }
    };

    float acc[2][8][4];
    #pragma unroll
    for (int mt = 0; mt < 2; ++mt)
        #pragma unroll
        for (int nt = 0; nt < 8; ++nt)
            #pragma unroll
            for (int e = 0; e < 4; ++e) acc[mt][nt][e] = 0.0f;

    const int wm = (wid >> 1) * 32;
    const int wn = (wid & 1) * 64;
    const int NC = E_ >> 5;

    load_stage(0, 0);
    cp_commit();

    for (int c = 0; c < NC; ++c) {
        if (c + 1 < NC) {
            load_stage((c + 1) & 1, (c + 1) * 32);
            cp_commit();
            cp_wait1();
        } else {
            cp_wait0();
        }
        __syncthreads();

        const uint32_t sb = smb + (uint32_t)(c & 1) * (QK_STAGE * 2);
        #pragma unroll
        for (int kk = 0; kk < 32; kk += 16) {
            uint32_t bh[8][2];
            #pragma unroll
            for (int ng = 0; ng < 4; ++ng) {
                const uint32_t addr = sb +
                    (uint32_t)((QK_SEG + (wn + ng * 16 + (lane & 15)) * QKSTRIDE
                                + kk + ((lane >> 4) << 3)) << 1);
                uint32_t r[4];
                LDSM_X4(r, addr);
                bh[2 * ng][0] = r[0]; bh[2 * ng][1] = r[2];
                bh[2 * ng + 1][0] = r[1]; bh[2 * ng + 1][1] = r[3];
            }
            uint32_t ah[2][4];
            #pragma unroll
            for (int mt = 0; mt < 2; ++mt) {
                const uint32_t addr = sb +
                    (uint32_t)(((wm + mt * 16 + (lane & 15)) * QKSTRIDE
                                + kk + ((lane >> 4) << 3)) << 1);
                LDSM_X4(ah[mt], addr);
            }
            #pragma unroll
            for (int mt = 0; mt < 2; ++mt)
                #pragma unroll
                for (int nt = 0; nt < 8; ++nt)
                    mma16816(acc[mt][nt], ah[mt], bh[nt][0], bh[nt][1]);
        }
        __syncthreads();
    }

    float pm[2][2];
    #pragma unroll
    for (int mt = 0; mt < 2; ++mt) { pm[mt][0] = -INFINITY; pm[mt][1] = -INFINITY; }
    #pragma unroll
    for (int mt = 0; mt < 2; ++mt)
        #pragma unroll
        for (int nt = 0; nt < 8; ++nt)
            #pragma unroll
            for (int e = 0; e < 4; ++e) {
                const int r = wm + mt * 16 + (lane >> 2) + (e >> 1) * 8;
                const int c = wn + nt * 8 + (lane & 3) * 2 + (e & 1);
                float v = acc[mt][nt][e] * 0.125f;
                if (c > r) v = -INFINITY;
                acc[mt][nt][e] = v;
                pm[mt][e >> 1] = fmaxf(pm[mt][e >> 1], v);
            }
    #pragma unroll
    for (int mt = 0; mt < 2; ++mt)
        #pragma unroll
        for (int rh = 0; rh < 2; ++rh) {
            pm[mt][rh] = fmaxf(pm[mt][rh], __shfl_xor_sync(0xffffffffu, pm[mt][rh], 1));
            pm[mt][rh] = fmaxf(pm[mt][rh], __shfl_xor_sync(0xffffffffu, pm[mt][rh], 2));
        }
    if ((lane & 3) == 0) {
        #pragma unroll
        for (int mt = 0; mt < 2; ++mt)
            #pragma unroll
            for (int rh = 0; rh < 2; ++rh)
                redmax[wid & 1][wm + mt * 16 + (lane >> 2) + rh * 8] = pm[mt][rh];
    }
    __syncthreads();

    float ps[2][2] = {{0.0f, 0.0f}, {0.0f, 0.0f}};
    float mrow[2][2];
    #pragma unroll
    for (int mt = 0; mt < 2; ++mt)
        #pragma unroll
        for (int rh = 0; rh < 2; ++rh) {
            const int r = wm + mt * 16 + (lane >> 2) + rh * 8;
            mrow[mt][rh] = fmaxf(redmax[0][r], redmax[1][r]);
        }
    #pragma unroll
    for (int mt = 0; mt < 2; ++mt)
        #pragma unroll
        for (int nt = 0; nt < 8; ++nt)
            #pragma unroll
            for (int e = 0; e < 4; ++e) {
                const float p = expf(acc[mt][nt][e] - mrow[mt][e >> 1]);
                acc[mt][nt][e] = p;
                ps[mt][e >> 1] += p;
            }
    #pragma unroll
    for (int mt = 0; mt < 2; ++mt)
        #pragma unroll
        for (int rh = 0; rh < 2; ++rh) {
            ps[mt][rh] += __shfl_xor_sync(0xffffffffu, ps[mt][rh], 1);
            ps[mt][rh] += __shfl_xor_sync(0xffffffffu, ps[mt][rh], 2);
        }
    if ((lane & 3) == 0) {
        #pragma unroll
        for (int mt = 0; mt < 2; ++mt)
            #pragma unroll
            for (int rh = 0; rh < 2; ++rh)
                redsum[wid & 1][wm + mt * 16 + (lane >> 2) + rh * 8] = ps[mt][rh];
    }
    __syncthreads();

    __half* Pb = P + (size_t)b * T_ * T_;
    #pragma unroll
    for (int mt = 0; mt < 2; ++mt)
        #pragma unroll
        for (int rh = 0; rh < 2; ++rh) {
            const int r = wm + mt * 16 + (lane >> 2) + rh * 8;
            const float inv = 1.0f / (redsum[0][r] + redsum[1][r]);
            #pragma unroll
            for (int nt = 0; nt < 8; ++nt) {
                const int c = wn + nt * 8 + (lane & 3) * 2;
                *(__half2*)(Pb + (size_t)r * T_ + c) =
                    __halves2half2(__float2half_rn(acc[mt][nt][rh * 2 + 0] * inv),
                                   __float2half_rn(acc[mt][nt][rh * 2 + 1] * inv));
            }
        }
}

// ---------------------------------------------------------------------------
// HMMA PV: O = X + P @ V. grid=(E/128, B), 256 threads, warp tile 32x64.
// P fp16 [t][s] (A, non-trans); V fp16 [s][e] (B via ldmatrix.trans, rows=s).
// K=128: single bulk load. Tiles are 128 rows x 128 halves = 16 chunks/row.
// ---------------------------------------------------------------------------
#define PVSTRIDE 136
#define PV_TILE_HALVES (128 * PVSTRIDE)       // 17408
static constexpr int PV_SMEM_BYTES = 2 * PV_TILE_HALVES * 2;  // 69632

__global__ __launch_bounds__(256, 2)
void pv_mma_kernel(const __half* __restrict__ P, const __half* __restrict__ V,
                   const float* __restrict__ X, float* __restrict__ O)
{
    extern __shared__ __half sm[];
    const int b  = blockIdx.y;
    const int n0 = blockIdx.x * 128;
    const int tid = threadIdx.x, wid = tid >> 5, lane = tid & 31;
    const uint32_t smb = smem_u32(sm);

    const __half* Pb = P + (size_t)b * T_ * T_;
    const __half* Vb = V + (size_t)b * T_ * E_ + n0;

    // FIXED loader: 4096 chunks total (2 tiles x 128 rows x 16 chunks of 16B)
    #pragma unroll
    for (int it = 0; it < 16; ++it) {
        const int i = tid + it * 256;            // 0..4095
        const int seg = i >> 11;                 // 0 P, 1 V
        const int j = i & 2047;
        const int row = j >> 4, ch = j & 15;
        const __half* src = seg == 0 ? (Pb + (size_t)row * T_ + ch * 8)
                                     : (Vb + (size_t)row * E_ + ch * 8);
        const uint32_t dst = smb +
            (uint32_t)((seg * PV_TILE_HALVES + row * PVSTRIDE + ch * 8) * 2);
        cp_async16(dst, src);
    }
    cp_commit();
    cp_wait0();
    __syncthreads();

    float acc[2][8][4];
    #pragma unroll
    for (int mt = 0; mt < 2; ++mt)
        #pragma unroll
        for (int nt = 0; nt < 8; ++nt)
            #pragma unroll
            for (int e = 0; e < 4; ++e) acc[mt][nt][e] = 0.0f;

    const int wm = (wid >> 1) * 32;
    const int wn = (wid & 1) * 64;

    #pragma unroll
    for (int kk = 0; kk < 128; kk += 16) {
        uint32_t bh[8][2];
        #pragma unroll
        for (int ng = 0; ng < 4; ++ng) {
            // trans load: smem rows = s (k), cols = e (n)
            // lanes 0-7: k+0..7 col+0 | 8-15: k+8..15 col+0
            // lanes 16-23: k+0..7 col+8 | 24-31: k+8..15 col+8
            const uint32_t addr = smb +
                (uint32_t)((PV_TILE_HALVES + (kk + (lane & 15)) * PVSTRIDE
                            + wn + ng * 16 + ((lane >> 4) << 3)) << 1);
            uint32_t r[4];
            LDSM_X4_T(r, addr);
            bh[2 * ng][0] = r[0]; bh[2 * ng][1] = r[1];
            bh[2 * ng + 1][0] = r[2]; bh[2 * ng + 1][1] = r[3];
        }
        uint32_t ah[2][4];
        #pragma unroll
        for (int mt = 0; mt < 2; ++mt) {
            const uint32_t addr = smb +
                (uint32_t)(((wm + mt * 16 + (lane & 15)) * PVSTRIDE
                            + kk + ((lane >> 4) << 3)) << 1);
            LDSM_X4(ah[mt], addr);
        }
        #pragma unroll
        for (int mt = 0; mt < 2; ++mt)
            #pragma unroll
            for (int nt = 0; nt < 8; ++nt)
                mma16816(acc[mt][nt], ah[mt], bh[nt][0], bh[nt][1]);
    }

    // epilogue: O = acc + X
    #pragma unroll
    for (int mt = 0; mt < 2; ++mt) {
        const int t0 = wm + mt * 16 + (lane >> 2);
        const int t1 = t0 + 8;
        const size_t g0 = ((size_t)b * T_ + t0) * E_;
        const size_t g1 = ((size_t)b * T_ + t1) * E_;
        #pragma unroll
        for (int nt = 0; nt < 8; ++nt) {
            const int col = n0 + wn + nt * 8 + (lane & 3) * 2;
            const float2 x0 = *(const float2*)(X + g0 + col);
            const float2 x1 = *(const float2*)(X + g1 + col);
            *(float2*)(O + g0 + col) = make_float2(acc[mt][nt][0] + x0.x,
                                                   acc[mt][nt][1] + x0.y);
            *(float2*)(O + g1 + col) = make_float2(acc[mt][nt][2] + x1.x,
                                                   acc[mt][nt][3] + x1.y);
        }
    }
}

// ---------------------------------------------------------------------------
// LayerNorm -> fp16 output
// ---------------------------------------------------------------------------
__global__ void ln_f16_kernel(const float* __restrict__ X,
                              const float* __restrict__ g,
                              const float* __restrict__ b,
                              __half* __restrict__ Ohi)
{
    const int row = blockIdx.x;
    const int tid = threadIdx.x;
    const int lane = tid & 31, wid = tid >> 5;

    const float4 v = ((const float4*)(X + (size_t)row * E_))[tid];
    float s  = v.x + v.y + v.z + v.w;
    float sq = v.x * v.x + v.y * v.y + v.z * v.z + v.w * v.w;

    #pragma unroll
    for (int off = 16; off > 0; off >>= 1) {
        s  += __shfl_xor_sync(0xffffffffu, s,  off);
        sq += __shfl_xor_sync(0xffffffffu, sq, off);
    }
    __shared__ float ss[4], ssq[4];
    if (lane == 0) { ss[wid] = s; ssq[wid] = sq; }
    __syncthreads();
    s  = ss[0]  + ss[1]  + ss[2]  + ss[3];
    sq = ssq[0] + ssq[1] + ssq[2] + ssq[3];

    const float mean = s * (1.0f / E_);
    const float var  = sq * (1.0f / E_) - mean * mean;
    const float inv  = rsqrtf(var + 1e-5f);

    const float4 gg = ((const float4*)g)[tid];
    const float4 bb = ((const float4*)b)[tid];
    const float o0 = (v.x - mean) * inv * gg.x + bb.x;
    const float o1 = (v.y - mean) * inv * gg.y + bb.y;
    const float o2 = (v.z - mean) * inv * gg.z + bb.z;
    const float o3 = (v.w - mean) * inv * gg.w + bb.w;

    __half2* ph = (__half2*)(Ohi + (size_t)row * E_);
    ph[tid * 2 + 0] = __halves2half2(__float2half_rn(o0), __float2half_rn(o1));
    ph[tid * 2 + 1] = __halves2half2(__float2half_rn(o2), __float2half_rn(o3));
}

// ---------------------------------------------------------------------------
// Merged transpose (fp32 -> fp16) for all 5 weights in ONE launch.
// ---------------------------------------------------------------------------
__global__ void transpose_all(
    const float* __restrict__ wq, const float* __restrict__ wk,
    const float* __restrict__ wv, const float* __restrict__ w1,
    const float* __restrict__ w2,
    __half* __restrict__ qt, __half* __restrict__ kt,
    __half* __restrict__ vt, __half* __restrict__ o1t,
    __half* __restrict__ o2t)
{
    __shared__ float tile[32][33];
    const int bid = blockIdx.x;
    const float* W; __half* Th;
    int Kdim, Ndim, t;
    if (bid < 768) {
        t = bid & 255; Kdim = E_; Ndim = E_;
        if (bid < 256)      { W = wq; Th = qt; }
        else if (bid < 512) { W = wk; Th = kt; }
        else                { W = wv; Th = vt; }
    } else if (bid < 1792) {
        t = bid - 768; Kdim = E_; Ndim = FF_;
        W = w1; Th = o1t;
    } else {
        t = bid - 1792; Kdim = FF_; Ndim = E_;
        W = w2; Th = o2t;
    }
    const int nblocks = Ndim / 32;
    const int n0 = (t % nblocks) * 32, k0 = (t / nblocks) * 32;
    const int tx = threadIdx.x, ty = threadIdx.y;   // (32, 8)
    #pragma unroll
    for (int i = 0; i < 4; ++i)
        tile[ty + i * 8][tx] = W[(size_t)(k0 + ty + i * 8) * Ndim + n0 + tx];
    __syncthreads();
    #pragma unroll
    for (int i = 0; i < 4; ++i) {
        const float v = tile[tx][ty + i * 8];
        const size_t o = (size_t)(n0 + ty + i * 8) * Kdim + k0 + tx;
        Th[o] = __float2half_rn(v);
    }
}

// ---------------------------------------------------------------------------
// Launch
// ---------------------------------------------------------------------------
extern "C" void kernel_launch(void* const* d_in, const int* in_sizes, int n_in,
                              void* d_out, int out_size)
{
    const float* x   = (const float*)d_in[0];
    const float* wq  = (const float*)d_in[1];
    const float* bq  = (const float*)d_in[2];
    const float* wk  = (const float*)d_in[3];
    const float* bk  = (const float*)d_in[4];
    const float* wv  = (const float*)d_in[5];
    const float* bv  = (const float*)d_in[6];
    const float* g1  = (const float*)d_in[7];
    const float* b1  = (const float*)d_in[8];
    const float* g2  = (const float*)d_in[9];
    const float* b2  = (const float*)d_in[10];
    const float* w1  = (const float*)d_in[11];
    const float* bm1 = (const float*)d_in[12];
    const float* w2  = (const float*)d_in[13];
    const float* bm2 = (const float*)d_in[14];
    float* out = (float*)d_out;

    __half *h_hi, *h2_hi, *m1_hi, *qh, *kh, *vh, *atth;
    __half *wqt, *wkt, *wvt, *w1t, *w2t;
    cudaGetSymbolAddress((void**)&h_hi,  g_h_hi);
    cudaGetSymbolAddress((void**)&h2_hi, g_h2_hi);
    cudaGetSymbolAddress((void**)&m1_hi, g_m1_hi);
    cudaGetSymbolAddress((void**)&qh, g_qh);
    cudaGetSymbolAddress((void**)&kh, g_kh);
    cudaGetSymbolAddress((void**)&vh, g_vh);
    cudaGetSymbolAddress((void**)&atth, g_atth);
    cudaGetSymbolAddress((void**)&wqt, g_wqt);
    cudaGetSymbolAddress((void**)&wkt, g_wkt);
    cudaGetSymbolAddress((void**)&wvt, g_wvt);
    cudaGetSymbolAddress((void**)&w1t, g_w1t);
    cudaGetSymbolAddress((void**)&w2t, g_w2t);

    cudaFuncSetAttribute(gemm_mma_kernel<0, 0>, cudaFuncAttributeMaxDynamicSharedMemorySize, GEMM_SMEM_BYTES);
    cudaFuncSetAttribute(gemm_mma_kernel<0, 1>, cudaFuncAttributeMaxDynamicSharedMemorySize, GEMM_SMEM_BYTES);
    cudaFuncSetAttribute(gemm_mma_kernel<1, 1>, cudaFuncAttributeMaxDynamicSharedMemorySize, GEMM_SMEM_BYTES);
    cudaFuncSetAttribute(qk_mma_softmax_kernel, cudaFuncAttributeMaxDynamicSharedMemorySize, QK_SMEM_BYTES);
    cudaFuncSetAttribute(pv_mma_kernel, cudaFuncAttributeMaxDynamicSharedMemorySize, PV_SMEM_BYTES);

    transpose_all<<<2816, dim3(32, 8)>>>(wq, wk, wv, w1, w2, wqt, wkt, wvt, w1t, w2t);

    ln_f16_kernel<<<ROWS, 128>>>(x, g1, b1, h_hi);

    const dim3 gQKV(E_ / GBN, ROWS / GBM);     // (4, 512)
    gemm_mma_kernel<0, 1><<<gQKV, 256, GEMM_SMEM_BYTES>>>(h_hi, wqt, bq, nullptr, nullptr, qh, E_, E_);
    gemm_mma_kernel<0, 1><<<gQKV, 256, GEMM_SMEM_BYTES>>>(h_hi, wkt, bk, nullptr, nullptr, kh, E_, E_);
    gemm_mma_kernel<0, 1><<<gQKV, 256, GEMM_SMEM_BYTES>>>(h_hi, wvt, bv, nullptr, nullptr, vh, E_, E_);

    qk_mma_softmax_kernel<<<B_, 256, QK_SMEM_BYTES>>>(qh, kh, atth);
    pv_mma_kernel<<<dim3(E_ / 128, B_), 256, PV_SMEM_BYTES>>>(atth, vh, x, out);

    ln_f16_kernel<<<ROWS, 128>>>(out, g2, b2, h2_hi);

    gemm_mma_kernel<1, 1><<<dim3(FF_ / GBN, ROWS / GBM), 256, GEMM_SMEM_BYTES>>>(
        h2_hi, w1t, bm1, nullptr, nullptr, m1_hi, FF_, E_);

    gemm_mma_kernel<0, 0><<<dim3(E_ / GBN, ROWS / GBM), 256, GEMM_SMEM_BYTES>>>(
        m1_hi, w2t, bm2, out, out, nullptr, E_, FF_);
}